// round 14
// baseline (speedup 1.0000x reference)
#include <cuda_runtime.h>

#define BB 8
#define NN 16384
#define NPT 2048
#define NS 32
#define ROWS (BB*NPT*NS)   /* 524288 */
#define EPSV 1e-5f
#define INV_ROWS (1.0f/524288.0f)
#define WPAD 68            /* u64 row stride: 2*68 % 32 == 8 -> conflict-free LDS.64 */
#define NBIN 2048

typedef unsigned long long ull;
typedef unsigned int u32;

// ---------------- static device scratch ----------------
__device__ float4 g_pxyz[BB*NN];                       // packed (x,y,z,0.5*|p|^2), orig order
__device__ float4 g_sx4[BB*NN];                        // x-sorted (x,y,z,0.5*|p|^2)
__device__ int    g_sorig[BB*NN];                      // x-sorted -> orig index
__device__ u32    g_xmm[BB*2];                         // per-batch mono(x) min/max
__device__ u32    g_hist[BB*NBIN];
__device__ u32    g_hoff[BB*NBIN];
__device__ u32    g_hcur[BB*NBIN];
__device__ float  g_ptst[(size_t)BB*NN*64];            // points transposed [b][n][c]
__device__ int    g_idx[BB*NPT*NS];                    // knn indices
__device__ float  g_h1[(size_t)ROWS*64];               // pre-BN layer1 out
__device__ float  g_h2[(size_t)ROWS*64];               // pre-BN layer2 out
__device__ float  g_mx[BB*NPT*128];                    // pre-BN pooled max
__device__ float  g_mn[BB*NPT*128];                    // pre-BN pooled min
__device__ float  g_stats[512];                        // S1 Q1 S2 Q2 S3[128] Q3[128]
__device__ ull    g_w1p[36*64];                        // paired hi-tf32 (b0,b1) [r][n]
__device__ ull    g_w2p[32*64];
__device__ ull    g_w3p[32*128];

// ---------------- helpers ----------------
__device__ __forceinline__ unsigned mono_map(float v) {
    unsigned u = __float_as_uint(v);
    return (u & 0x80000000u) ? ~u : (u | 0x80000000u);
}
__device__ __forceinline__ float unmono(u32 m) {
    u32 bits = (m & 0x80000000u) ? (m & 0x7FFFFFFFu) : ~m;
    return __uint_as_float(bits);
}
__device__ __forceinline__ void binparams(int b, float& xmin, float& scale, float& bw) {
    xmin = unmono(g_xmm[b*2+0]);
    float xmax = unmono(g_xmm[b*2+1]);
    float range = fmaxf(xmax - xmin, 1e-6f);
    scale = ((float)NBIN / range) * 0.999999f;
    bw = range * (1.0f/(float)NBIN) * 1.001f + 1e-7f;   // conservative >= true bin width
}

__device__ __forceinline__ u32 f2tf32(float f) {
    u32 r;
    asm("cvt.rna.tf32.f32 %0, %1;" : "=r"(r) : "f"(f));
    return r;
}
__device__ __forceinline__ void tf32_split(float f, u32& hi, u32& lo) {
    hi = f2tf32(f);
    lo = f2tf32(f - __uint_as_float(hi));
}
__device__ __forceinline__ void mma_tf32(float& d0, float& d1, float& d2, float& d3,
                                         u32 a0, u32 a1, u32 a2, u32 a3,
                                         u32 b0, u32 b1) {
    asm volatile(
        "mma.sync.aligned.m16n8k8.row.col.f32.tf32.tf32.f32 "
        "{%0,%1,%2,%3}, {%4,%5,%6,%7}, {%8,%9}, {%0,%1,%2,%3};\n"
        : "+f"(d0), "+f"(d1), "+f"(d2), "+f"(d3)
        : "r"(a0), "r"(a1), "r"(a2), "r"(a3), "r"(b0), "r"(b1));
}

// ---------------- init: reset per-batch x min/max ----------------
__global__ void k_init() {
    int t = threadIdx.x;
    if (t < BB) { g_xmm[t*2] = 0xFFFFFFFFu; g_xmm[t*2+1] = 0u; }
}

// ---------------- prep: stats/hist zero + pxyz pack + x-minmax + gatherq + weights ----
__global__ void k_prep(const float* __restrict__ xyz,
                       const int* __restrict__ sidx,
                       const float* __restrict__ W1, const float* __restrict__ W2,
                       const float* __restrict__ W3, float* __restrict__ outq) {
    int i = blockIdx.x*256 + threadIdx.x;
    if (i < 512) g_stats[i] = 0.0f;
    if (i < BB*NBIN) g_hist[i] = 0u;
    if (i < BB*3*NPT) {
        int p = i & (NPT-1);
        int bc = i >> 11;
        outq[i] = xyz[bc*NN + sidx[p]];
    }
    float xv = 0.0f;
    if (i < BB*NN) {
        int b = i >> 14, n = i & (NN-1);
        float x = xyz[(b*3+0)*NN + n];
        float y = xyz[(b*3+1)*NN + n];
        float z = xyz[(b*3+2)*NN + n];
        g_pxyz[i] = make_float4(x, y, z, 0.5f*(x*x + y*y + z*z));
        xv = x;
    } else {
        int wi = i - BB*NN;
        if (wi < 36*64) {
            int r = wi >> 6, n = wi & 63;
            int k = r >> 2, c = r & 3;
            int kk0 = 8*k + c, kk1 = kk0 + 4;
            float w0 = 0.0f, w1 = 0.0f;
            if (kk0 < 64)      w0 = W1[n*67 + 3 + kk0];
            else if (kk0 < 67) w0 = W1[n*67 + (kk0 - 64)];
            if (kk1 < 64)      w1 = W1[n*67 + 3 + kk1];
            else if (kk1 < 67) w1 = W1[n*67 + (kk1 - 64)];
            g_w1p[wi] = ((ull)f2tf32(w1) << 32) | f2tf32(w0);
        } else if (wi < 36*64 + 32*64) {
            int j = wi - 36*64;
            int r = j >> 6, n = j & 63;
            int k = r >> 2, c = r & 3;
            g_w2p[j] = ((ull)f2tf32(W2[n*64 + 8*k + c + 4]) << 32)
                     | f2tf32(W2[n*64 + 8*k + c]);
        } else if (wi < 36*64 + 32*64 + 32*128) {
            int j = wi - 36*64 - 32*64;
            int r = j >> 7, n = j & 127;
            int k = r >> 2, c = r & 3;
            g_w3p[j] = ((ull)f2tf32(W3[n*64 + 8*k + c + 4]) << 32)
                     | f2tf32(W3[n*64 + 8*k + c]);
        }
    }
    if (blockIdx.x < (BB*NN)/256) {
        u32 umin = mono_map(xv), umax = umin;
        #pragma unroll
        for (int m = 16; m > 0; m >>= 1) {
            umin = min(umin, __shfl_xor_sync(0xffffffffu, umin, m));
            umax = max(umax, __shfl_xor_sync(0xffffffffu, umax, m));
        }
        __shared__ u32 smin[8], smax[8];
        if ((threadIdx.x & 31) == 0) { smin[threadIdx.x>>5] = umin; smax[threadIdx.x>>5] = umax; }
        __syncthreads();
        if (threadIdx.x == 0) {
            u32 mn = smin[0], mx = smax[0];
            #pragma unroll
            for (int j = 1; j < 8; ++j) { mn = min(mn, smin[j]); mx = max(mx, smax[j]); }
            int b = (blockIdx.x*256) >> 14;
            atomicMin(&g_xmm[b*2+0], mn);
            atomicMax(&g_xmm[b*2+1], mx);
        }
    }
}

// ---------------- histogram of x bins ----------------
__global__ __launch_bounds__(256) void k_hist() {
    int i = blockIdx.x*256 + threadIdx.x;   // < BB*NN
    int b = i >> 14;
    float xmin, scale, bw;
    binparams(b, xmin, scale, bw);
    float x = g_pxyz[i].x;
    int bin = (int)((x - xmin)*scale);
    bin = min(NBIN-1, max(0, bin));
    atomicAdd(&g_hist[b*NBIN + bin], 1u);
}

// ---------------- exclusive prefix over NBIN bins, one block per batch ----------------
__global__ __launch_bounds__(512) void k_scan() {
    int b = blockIdx.x, tid = threadIdx.x, lane = tid & 31, wp = tid >> 5;
    int base = b*NBIN + tid*4;
    u32 v0 = g_hist[base], v1 = g_hist[base+1], v2 = g_hist[base+2], v3 = g_hist[base+3];
    u32 tot = v0 + v1 + v2 + v3;
    u32 inc = tot;
    #pragma unroll
    for (int d = 1; d < 32; d <<= 1) {
        u32 o = __shfl_up_sync(0xffffffffu, inc, d);
        if (lane >= d) inc += o;
    }
    __shared__ u32 ws[16];
    if (lane == 31) ws[wp] = inc;
    __syncthreads();
    if (tid < 16) {
        u32 x = ws[tid];
        u32 ix = x;
        #pragma unroll
        for (int d = 1; d < 16; d <<= 1) {
            u32 o = __shfl_up_sync(0xffffu, ix, d);
            if (tid >= d) ix += o;
        }
        ws[tid] = ix - x;  // exclusive
    }
    __syncthreads();
    u32 excl = ws[wp] + inc - tot;
    g_hoff[base] = excl;           g_hcur[base] = excl;
    g_hoff[base+1] = excl+v0;      g_hcur[base+1] = excl+v0;
    g_hoff[base+2] = excl+v0+v1;   g_hcur[base+2] = excl+v0+v1;
    g_hoff[base+3] = excl+v0+v1+v2; g_hcur[base+3] = excl+v0+v1+v2;
}

// ---------------- scatter points into x-sorted order ----------------
__global__ __launch_bounds__(256) void k_scatter() {
    int i = blockIdx.x*256 + threadIdx.x;   // < BB*NN
    int b = i >> 14, n = i & (NN-1);
    float xmin, scale, bw;
    binparams(b, xmin, scale, bw);
    float4 P = g_pxyz[i];
    int bin = (int)((P.x - xmin)*scale);
    bin = min(NBIN-1, max(0, bin));
    u32 pos = atomicAdd(&g_hcur[b*NBIN + bin], 1u);
    g_sx4[(size_t)b*NN + pos] = P;
    g_sorig[(size_t)b*NN + pos] = n;
}

// ---------------- warp 64-bit shuffles ----------------
__device__ __forceinline__ ull shfl_xor_u64(ull v, int m) {
    u32 lo = (u32)v, hi = (u32)(v >> 32);
    lo = __shfl_xor_sync(0xffffffffu, lo, m);
    hi = __shfl_xor_sync(0xffffffffu, hi, m);
    return ((ull)hi << 32) | lo;
}
__device__ __forceinline__ ull shfl_idx_u64(ull v, int src) {
    u32 lo = (u32)v, hi = (u32)(v >> 32);
    lo = __shfl_sync(0xffffffffu, lo, src);
    hi = __shfl_sync(0xffffffffu, hi, src);
    return ((ull)hi << 32) | lo;
}

// ---------------- bitonic sort of 32 ull (1/lane), ascending ----------------
__device__ __forceinline__ ull bitonic_sort32(ull v, int lane) {
    #pragma unroll
    for (int k = 2; k <= 32; k <<= 1) {
        #pragma unroll
        for (int j = k >> 1; j > 0; j >>= 1) {
            ull o = shfl_xor_u64(v, j);
            bool lower  = (lane & j) == 0;
            bool dirUp  = (lane & k) == 0;
            bool takeMin = (lower == dirUp);
            bool sw = takeMin ? (o < v) : (o > v);
            v = sw ? o : v;
        }
    }
    return v;
}

// ---------------- knn flush: bitonic top-32 merge of buffered candidates ----------
__device__ __forceinline__ void knn_flush(ull& top, int& cnt, float& thr,
                                          ull* cb, int lane) {
    for (int base = 0; base < cnt; base += 32) {
        int idx = base + lane;
        ull s = (idx < cnt) ? cb[idx] : ~0ull;
        s = bitonic_sort32(s, lane);                 // ascending
        ull r = shfl_idx_u64(s, 31 - lane);          // descending
        ull m = (top < r) ? top : r;                 // bitonic; holds 32 smallest
        #pragma unroll
        for (int j = 16; j > 0; j >>= 1) {           // clean -> ascending
            ull o = shfl_xor_u64(m, j);
            bool lower = (lane & j) == 0;
            bool sw = lower ? (o < m) : (o > m);
            m = sw ? o : m;
        }
        top = m;
    }
    cnt = 0;
    ull k31 = shfl_idx_u64(top, 31);
    unsigned u = (unsigned)(k31 >> 32);
    float t;
    if (u == 0xFFFFFFFFu) {
        t = __int_as_float(0x7F800000);  // +inf
    } else {
        unsigned bits = (u & 0x80000000u) ? (u & 0x7FFFFFFFu) : ~u;
        t = __uint_as_float(bits);
    }
    thr = t;
}

// ---------------- knn on x-sorted points: two-phase bulk window, 1 query/warp ------
__global__ __launch_bounds__(256) void k_knn2(const int* __restrict__ sidx) {
    __shared__ ull cbuf[8*128];                      // 8KB
    int tid = threadIdx.x, lane = tid & 31, w = tid >> 5;
    int b = blockIdx.y;
    unsigned lml = (1u << lane) - 1u;
    ull* cb = &cbuf[w*128];

    int qg = blockIdx.x*8 + w;
    int s = sidx[qg];
    float4 Q = g_pxyz[b*NN + s];
    float qx = Q.x, qy = Q.y, qz = Q.z, c2 = Q.w;

    float xmin, scale, bw;
    binparams(b, xmin, scale, bw);
    int qbin = min(NBIN-1, max(0, (int)((qx - xmin)*scale)));
    int start = (int)g_hoff[b*NBIN + qbin];

    const float4* px = &g_sx4[(size_t)b*NN];
    const int* porig = &g_sorig[(size_t)b*NN];

    const float INFF = __int_as_float(0x7F800000);
    ull top = ~0ull;
    float thr = INFF, u = INFF;
    int cnt = 0;

    // ---- phase 1: fixed 64-point aligned window around start ----
    int s0 = (start - 32) & ~31;
    s0 = min(max(s0, 0), NN - 64);
    #pragma unroll
    for (int h = 0; h < 2; ++h) {
        int j = s0 + h*32 + lane;
        float4 p = __ldg(&px[j]);
        float d = __fmaf_rn(-qx, p.x, p.w);
        d = __fmaf_rn(-qy, p.y, d);
        d = __fmaf_rn(-qz, p.z, d);
        unsigned m = __ballot_sync(0xffffffffu, true);
        unsigned ub = mono_map(d + c2);
        cb[cnt + lane] = ((ull)ub << 32) | (unsigned)__ldg(&porig[j]);
        cnt += 32; (void)m;
    }
    knn_flush(top, cnt, thr, cb, lane);
    u = __fadd_ru(thr, -c2);

    // ---- exact conservative window from phase-1 bound ----
    float r = sqrtf(fmaxf(2.0f*thr, 0.0f)) * 1.0001f + bw;
    int blo = min(NBIN-1, max(0, (int)((qx - r - xmin)*scale) - 1));
    int bhi = min(NBIN-1, max(0, (int)((qx + r - xmin)*scale) + 1));
    int lo = (int)g_hoff[b*NBIN + blo];
    int hi = (bhi >= NBIN-1) ? NN : (int)g_hoff[b*NBIN + bhi + 1];

    // ---- phase 2a: [lo, s0) ----
    for (int base = lo & ~31; base < s0; base += 32) {
        if (cnt > 96) { knn_flush(top, cnt, thr, cb, lane); u = __fadd_ru(thr, -c2); }
        int j = base + lane;
        bool valid = (j >= lo);
        float4 p = __ldg(&px[j]);            // base >= 0, j < s0 <= NN
        float d = __fmaf_rn(-qx, p.x, p.w);
        d = __fmaf_rn(-qy, p.y, d);
        d = __fmaf_rn(-qz, p.z, d);
        bool pr = valid && (d < u);
        unsigned m = __ballot_sync(0xffffffffu, pr);
        if (m) {
            if (pr) {
                unsigned ub = mono_map(d + c2);
                cb[cnt + __popc(m & lml)] = ((ull)ub << 32) | (unsigned)__ldg(&porig[j]);
            }
            cnt += __popc(m);
        }
    }
    // ---- phase 2b: [s0+64, hi) ----
    for (int base = s0 + 64; base < hi; base += 32) {
        if (cnt > 96) { knn_flush(top, cnt, thr, cb, lane); u = __fadd_ru(thr, -c2); }
        int j = base + lane;
        bool valid = (j < hi);
        int jc = min(j, NN-1);
        float4 p = __ldg(&px[jc]);
        float d = __fmaf_rn(-qx, p.x, p.w);
        d = __fmaf_rn(-qy, p.y, d);
        d = __fmaf_rn(-qz, p.z, d);
        bool pr = valid && (d < u);
        unsigned m = __ballot_sync(0xffffffffu, pr);
        if (m) {
            if (pr) {
                unsigned ub = mono_map(d + c2);
                cb[cnt + __popc(m & lml)] = ((ull)ub << 32) | (unsigned)__ldg(&porig[jc]);
            }
            cnt += __popc(m);
        }
    }
    knn_flush(top, cnt, thr, cb, lane);
    g_idx[(b*NPT + qg)*NS + lane] = (int)(top & 0xffffffffu);
}

// ---------------- tiled transpose points (B,C,N) -> (B,N,C), coalesced both ways ----
__global__ __launch_bounds__(256) void k_xpose(const float* __restrict__ pts) {
    __shared__ float tile[64*129];
    int blk = blockIdx.x;
    int b = blk >> 7;
    int nbase = (blk & 127) * 128;
    int tid = threadIdx.x;
    int nl = tid & 127, rh = tid >> 7;
    #pragma unroll
    for (int pass = 0; pass < 32; ++pass) {
        int row = rh + pass*2;
        tile[row*129 + nl] = pts[((size_t)(b*64 + row))*NN + nbase + nl];
    }
    __syncthreads();
    int cg = (tid & 15) * 4, nh = tid >> 4;
    #pragma unroll
    for (int pass = 0; pass < 8; ++pass) {
        int n = nh + pass*16;
        float4 v = make_float4(tile[cg*129 + n], tile[(cg+1)*129 + n],
                               tile[(cg+2)*129 + n], tile[(cg+3)*129 + n]);
        *(float4*)&g_ptst[((size_t)(b*NN + nbase + n))*64 + cg] = v;
    }
}

// ============================================================================
// Layer kernels: k-OUTER loop, in-place accumulation into acc[8][4] (32 regs).
// ============================================================================

#define LAYER_STATS_EPI(d0,d1,d2,d3,hout,stride,ooff,nn8)                         \
    do {                                                                          \
        *(float2*)&hout[row0*stride + ooff + (nn8)*8 + 2*c] = make_float2(d0, d1);\
        *(float2*)&hout[row1*stride + ooff + (nn8)*8 + 2*c] = make_float2(d2, d3);\
        float s0 = d0 + d2, s1 = d1 + d3;                                         \
        float q0 = d0*d0 + d2*d2, q1 = d1*d1 + d3*d3;                             \
        _Pragma("unroll")                                                         \
        for (int m = 4; m <= 16; m <<= 1) {                                       \
            s0 += __shfl_xor_sync(0xffffffffu, s0, m);                            \
            s1 += __shfl_xor_sync(0xffffffffu, s1, m);                            \
            q0 += __shfl_xor_sync(0xffffffffu, q0, m);                            \
            q1 += __shfl_xor_sync(0xffffffffu, q1, m);                            \
        }                                                                         \
        if (lane < 4) {                                                           \
            int col0 = (nn8)*8 + 2*c;                                             \
            sm_s[w*64 + col0] = s0; sm_s[w*64 + col0 + 1] = s1;                   \
            sm_q[w*64 + col0] = q0; sm_q[w*64 + col0 + 1] = q1;                   \
        }                                                                         \
    } while (0)

__global__ __launch_bounds__(256, 3) void k_layer1(const float* __restrict__ xyz,
                                                   const int* __restrict__ sidx,
                                                   const float* __restrict__ b1) {
    __shared__ ull ws64[36*WPAD];
    __shared__ float bs[64];
    __shared__ float sm_s[512], sm_q[512];
    int tid = threadIdx.x;
    for (int i = tid; i < 36*64; i += 256)
        ws64[(i >> 6)*WPAD + (i & 63)] = g_w1p[i];
    if (tid < 64) bs[tid] = b1[tid];
    __syncthreads();

    int lane = tid & 31, w = tid >> 5;
    int g = lane >> 2, c = lane & 3;
    size_t row0 = (size_t)blockIdx.x*128 + w*16 + g;
    size_t row1 = row0 + 8;
    int b = (int)(row0 >> 16);
    int n0 = g_idx[row0], n1 = g_idx[row1];
    int p0 = ((int)row0 >> 5) & (NPT-1);
    int s = sidx[p0];
    float qx = xyz[(b*3+0)*NN + s], qy = xyz[(b*3+1)*NN + s], qz = xyz[(b*3+2)*NN + s];
    float4 P0 = g_pxyz[b*NN + n0];
    float4 P1 = g_pxyz[b*NN + n1];
    const float* f0 = &g_ptst[(size_t)(b*NN + n0)*64];
    const float* f1 = &g_ptst[(size_t)(b*NN + n1)*64];

    float acc[8][4];
    #pragma unroll
    for (int n8 = 0; n8 < 8; ++n8) {
        acc[n8][0] = bs[n8*8 + 2*c]; acc[n8][1] = bs[n8*8 + 2*c + 1];
        acc[n8][2] = acc[n8][0];     acc[n8][3] = acc[n8][1];
    }

    const ull* pb = &ws64[c*WPAD + g];
    #pragma unroll
    for (int k = 0; k < 9; ++k) {
        u32 a0h, a0l, a1h, a1l, a2h, a2l, a3h, a3l;
        if (k < 8) {
            int col0 = c + 8*k, col1 = col0 + 4;
            float x00 = __ldg(&f0[col0]);
            float x10 = __ldg(&f1[col0]);
            float x01 = __ldg(&f0[col1]);
            float x11 = __ldg(&f1[col1]);
            tf32_split(x00, a0h, a0l);
            tf32_split(x10, a1h, a1l);
            tf32_split(x01, a2h, a2l);
            tf32_split(x11, a3h, a3l);
        } else {
            float e0 = (c == 0) ? (P0.x - qx) : (c == 1) ? (P0.y - qy) : (c == 2) ? (P0.z - qz) : 0.0f;
            float e1 = (c == 0) ? (P1.x - qx) : (c == 1) ? (P1.y - qy) : (c == 2) ? (P1.z - qz) : 0.0f;
            tf32_split(e0, a0h, a0l);
            tf32_split(e1, a1h, a1l);
            a2h = 0; a2l = 0; a3h = 0; a3l = 0;
        }
        #pragma unroll
        for (int n8 = 0; n8 < 8; ++n8) {
            ull wv = pb[k*4*WPAD + n8*8];
            u32 b0 = (u32)wv, b1v = (u32)(wv >> 32);
            mma_tf32(acc[n8][0],acc[n8][1],acc[n8][2],acc[n8][3], a0h,a1h,a2h,a3h, b0,b1v);
            mma_tf32(acc[n8][0],acc[n8][1],acc[n8][2],acc[n8][3], a0l,a1l,a2l,a3l, b0,b1v);
        }
    }
    #pragma unroll
    for (int n8 = 0; n8 < 8; ++n8)
        LAYER_STATS_EPI(acc[n8][0],acc[n8][1],acc[n8][2],acc[n8][3], g_h1, 64, 0, n8);
    __syncthreads();
    if (tid < 64) {
        float S = 0.0f, Q = 0.0f;
        #pragma unroll
        for (int ww = 0; ww < 8; ++ww) { S += sm_s[ww*64 + tid]; Q += sm_q[ww*64 + tid]; }
        atomicAdd(&g_stats[tid], S);
        atomicAdd(&g_stats[64 + tid], Q);
    }
}

__global__ __launch_bounds__(256, 3) void k_layer2(const float* __restrict__ b2,
                                                   const float* __restrict__ g1,
                                                   const float* __restrict__ be1) {
    __shared__ ull ws64[32*WPAD];
    __shared__ float bs[64], sc[64], sh[64];
    __shared__ float sm_s[512], sm_q[512];
    int tid = threadIdx.x;
    for (int i = tid; i < 32*64; i += 256)
        ws64[(i >> 6)*WPAD + (i & 63)] = g_w2p[i];
    if (tid < 64) {
        bs[tid] = b2[tid];
        float m = g_stats[tid] * INV_ROWS;
        float v = g_stats[64+tid] * INV_ROWS - m*m;
        float scv = g1[tid] * rsqrtf(v + EPSV);
        sc[tid] = scv;
        sh[tid] = be1[tid] - m*scv;
    }
    __syncthreads();

    int lane = tid & 31, w = tid >> 5;
    int g = lane >> 2, c = lane & 3;
    size_t row0 = (size_t)blockIdx.x*128 + w*16 + g;
    size_t row1 = row0 + 8;
    const float* h0 = &g_h1[row0*64];
    const float* h1p = &g_h1[row1*64];

    float acc[8][4];
    #pragma unroll
    for (int n8 = 0; n8 < 8; ++n8) {
        acc[n8][0] = bs[n8*8 + 2*c]; acc[n8][1] = bs[n8*8 + 2*c + 1];
        acc[n8][2] = acc[n8][0];     acc[n8][3] = acc[n8][1];
    }

    const ull* pb = &ws64[c*WPAD + g];
    #pragma unroll
    for (int k = 0; k < 8; ++k) {
        int col0 = c + 8*k, col1 = col0 + 4;
        float sc0 = sc[col0], sh0 = sh[col0];
        float sc1 = sc[col1], sh1 = sh[col1];
        float x00 = fmaxf(__ldg(&h0[col0])*sc0 + sh0, 0.0f);
        float x10 = fmaxf(__ldg(&h1p[col0])*sc0 + sh0, 0.0f);
        float x01 = fmaxf(__ldg(&h0[col1])*sc1 + sh1, 0.0f);
        float x11 = fmaxf(__ldg(&h1p[col1])*sc1 + sh1, 0.0f);
        u32 a0h, a0l, a1h, a1l, a2h, a2l, a3h, a3l;
        tf32_split(x00, a0h, a0l);
        tf32_split(x10, a1h, a1l);
        tf32_split(x01, a2h, a2l);
        tf32_split(x11, a3h, a3l);
        #pragma unroll
        for (int n8 = 0; n8 < 8; ++n8) {
            ull wv = pb[k*4*WPAD + n8*8];
            u32 b0 = (u32)wv, b1v = (u32)(wv >> 32);
            mma_tf32(acc[n8][0],acc[n8][1],acc[n8][2],acc[n8][3], a0h,a1h,a2h,a3h, b0,b1v);
            mma_tf32(acc[n8][0],acc[n8][1],acc[n8][2],acc[n8][3], a0l,a1l,a2l,a3l, b0,b1v);
        }
    }
    #pragma unroll
    for (int n8 = 0; n8 < 8; ++n8)
        LAYER_STATS_EPI(acc[n8][0],acc[n8][1],acc[n8][2],acc[n8][3], g_h2, 64, 0, n8);
    __syncthreads();
    if (tid < 64) {
        float S = 0.0f, Q = 0.0f;
        #pragma unroll
        for (int ww = 0; ww < 8; ++ww) { S += sm_s[ww*64 + tid]; Q += sm_q[ww*64 + tid]; }
        atomicAdd(&g_stats[128 + tid], S);
        atomicAdd(&g_stats[192 + tid], Q);
    }
}

#define POOL_EPI(d0,d1,d2,d3,nn8)                                                 \
    do {                                                                          \
        float mx0 = fmaxf(d0, d2), mn0 = fminf(d0, d2);                           \
        float mx1 = fmaxf(d1, d3), mn1 = fminf(d1, d3);                           \
        float s0 = d0 + d2, s1 = d1 + d3;                                         \
        float q0 = d0*d0 + d2*d2, q1 = d1*d1 + d3*d3;                             \
        _Pragma("unroll")                                                         \
        for (int m = 4; m <= 16; m <<= 1) {                                       \
            mx0 = fmaxf(mx0, __shfl_xor_sync(0xffffffffu, mx0, m));               \
            mn0 = fminf(mn0, __shfl_xor_sync(0xffffffffu, mn0, m));               \
            mx1 = fmaxf(mx1, __shfl_xor_sync(0xffffffffu, mx1, m));               \
            mn1 = fminf(mn1, __shfl_xor_sync(0xffffffffu, mn1, m));               \
            s0 += __shfl_xor_sync(0xffffffffu, s0, m);                            \
            s1 += __shfl_xor_sync(0xffffffffu, s1, m);                            \
            q0 += __shfl_xor_sync(0xffffffffu, q0, m);                            \
            q1 += __shfl_xor_sync(0xffffffffu, q1, m);                            \
        }                                                                         \
        if (lane < 4) {                                                           \
            int col0 = (nn8)*8 + 2*c;                                             \
            sm_mx[w*64 + col0] = mx0; sm_mx[w*64 + col0 + 1] = mx1;               \
            sm_mn[w*64 + col0] = mn0; sm_mn[w*64 + col0 + 1] = mn1;               \
            sm_s[w*64 + col0] = s0;   sm_s[w*64 + col0 + 1] = s1;                 \
            sm_q[w*64 + col0] = q0;   sm_q[w*64 + col0 + 1] = q1;                 \
        }                                                                         \
    } while (0)

__global__ __launch_bounds__(256, 3) void k_layer3(const float* __restrict__ b3,
                                                   const float* __restrict__ g2,
                                                   const float* __restrict__ be2) {
    __shared__ ull ws64[64*WPAD];
    __shared__ float bs[128], sc[64], sh[64];
    __shared__ float sm_mx[512], sm_mn[512], sm_s[512], sm_q[512];
    int tid = threadIdx.x;
    int lane = tid & 31, w = tid >> 5;
    int g = lane >> 2, c = lane & 3;

    for (int i = tid; i < 32*128; i += 256) {
        int r = i >> 7, n = i & 127;
        ws64[(n >> 6)*32*WPAD + r*WPAD + (n & 63)] = g_w3p[i];
    }
    if (tid < 128) bs[tid] = b3[tid];
    if (tid < 64) {
        float m = g_stats[128+tid] * INV_ROWS;
        float v = g_stats[192+tid] * INV_ROWS - m*m;
        float scv = g2[tid] * rsqrtf(v + EPSV);
        sc[tid] = scv;
        sh[tid] = be2[tid] - m*scv;
    }
    __syncthreads();

    size_t row0 = (size_t)blockIdx.x*128 + w*16 + g;
    size_t row1 = row0 + 8;
    const float* h0 = &g_h2[row0*64];
    const float* h1p = &g_h2[row1*64];

    #pragma unroll
    for (int oh = 0; oh < 2; ++oh) {
        if (oh == 1) __syncthreads();
        const ull* pb = &ws64[oh*32*WPAD + c*WPAD + g];
        float acc[8][4];
        #pragma unroll
        for (int n8 = 0; n8 < 8; ++n8) {
            acc[n8][0] = bs[oh*64 + n8*8 + 2*c]; acc[n8][1] = bs[oh*64 + n8*8 + 2*c + 1];
            acc[n8][2] = acc[n8][0];             acc[n8][3] = acc[n8][1];
        }
        #pragma unroll
        for (int k = 0; k < 8; ++k) {
            int col0 = c + 8*k, col1 = col0 + 4;
            float sc0 = sc[col0], sh0 = sh[col0];
            float sc1 = sc[col1], sh1 = sh[col1];
            float x00 = fmaxf(__ldg(&h0[col0])*sc0 + sh0, 0.0f);
            float x10 = fmaxf(__ldg(&h1p[col0])*sc0 + sh0, 0.0f);
            float x01 = fmaxf(__ldg(&h0[col1])*sc1 + sh1, 0.0f);
            float x11 = fmaxf(__ldg(&h1p[col1])*sc1 + sh1, 0.0f);
            u32 a0h, a0l, a1h, a1l, a2h, a2l, a3h, a3l;
            tf32_split(x00, a0h, a0l);
            tf32_split(x10, a1h, a1l);
            tf32_split(x01, a2h, a2l);
            tf32_split(x11, a3h, a3l);
            #pragma unroll
            for (int n8 = 0; n8 < 8; ++n8) {
                ull wv = pb[k*4*WPAD + n8*8];
                u32 b0 = (u32)wv, b1v = (u32)(wv >> 32);
                mma_tf32(acc[n8][0],acc[n8][1],acc[n8][2],acc[n8][3], a0h,a1h,a2h,a3h, b0,b1v);
                mma_tf32(acc[n8][0],acc[n8][1],acc[n8][2],acc[n8][3], a0l,a1l,a2l,a3l, b0,b1v);
            }
        }
        #pragma unroll
        for (int n8 = 0; n8 < 8; ++n8)
            POOL_EPI(acc[n8][0],acc[n8][1],acc[n8][2],acc[n8][3], n8);
        __syncthreads();
        {
            int ct = tid >> 6, col = tid & 63;
            float mx = fmaxf(sm_mx[(2*ct)*64 + col], sm_mx[(2*ct+1)*64 + col]);
            float mn = fminf(sm_mn[(2*ct)*64 + col], sm_mn[(2*ct+1)*64 + col]);
            size_t bpos = (size_t)blockIdx.x*4 + ct;
            g_mx[bpos*128 + oh*64 + col] = mx;
            g_mn[bpos*128 + oh*64 + col] = mn;
            if (tid < 64) {
                float S = 0.0f, Q = 0.0f;
                #pragma unroll
                for (int ww = 0; ww < 8; ++ww) { S += sm_s[ww*64 + tid]; Q += sm_q[ww*64 + tid]; }
                atomicAdd(&g_stats[256 + oh*64 + tid], S);
                atomicAdd(&g_stats[384 + oh*64 + tid], Q);
            }
        }
    }
}

// ---------------- apply BN3 affine to pooled max/min, transpose-store ----------------
__global__ __launch_bounds__(256) void k_apply(const float* __restrict__ g3,
                                               const float* __restrict__ be3,
                                               float* __restrict__ outp) {
    int i = blockIdx.x*256 + threadIdx.x;      // 16384*128
    int c = i & 127;
    int bp = i >> 7;
    int b = bp >> 11, p = bp & (NPT-1);
    float m = g_stats[256+c] * INV_ROWS;
    float v = g_stats[384+c] * INV_ROWS - m*m;
    float scv = g3[c] * rsqrtf(v + EPSV);
    float sh = be3[c] - m*scv;
    float pick = (scv >= 0.0f) ? g_mx[i] : g_mn[i];
    outp[((size_t)b*128 + c)*NPT + p] = pick*scv + sh;
}

// ---------------- launch ----------------
extern "C" void kernel_launch(void* const* d_in, const int* in_sizes, int n_in,
                              void* d_out, int out_size) {
    const float* xyz    = (const float*)d_in[0];
    const float* points = (const float*)d_in[1];
    const int*   sidx   = (const int*)d_in[2];
    const float* W1 = (const float*)d_in[3];
    const float* b1 = (const float*)d_in[4];
    const float* g1 = (const float*)d_in[5];
    const float* be1 = (const float*)d_in[6];
    const float* W2 = (const float*)d_in[7];
    const float* b2 = (const float*)d_in[8];
    const float* g2 = (const float*)d_in[9];
    const float* be2 = (const float*)d_in[10];
    const float* W3 = (const float*)d_in[11];
    const float* b3 = (const float*)d_in[12];
    const float* g3 = (const float*)d_in[13];
    const float* be3 = (const float*)d_in[14];

    float* outq = (float*)d_out;                 // (B,3,NPT)
    float* outp = outq + (size_t)BB*3*NPT;       // (B,128,NPT)

    const int prep_total = BB*NN + 36*64 + 32*64 + 32*128;
    k_init<<<1, 32>>>();
    k_prep<<<(prep_total + 255)/256, 256>>>(xyz, sidx, W1, W2, W3, outq);
    k_xpose<<<BB*NN/128, 256>>>(points);
    k_hist<<<BB*NN/256, 256>>>();
    k_scan<<<BB, 512>>>();
    k_scatter<<<BB*NN/256, 256>>>();
    k_knn2<<<dim3(NPT/8, BB), 256>>>(sidx);
    k_layer1<<<ROWS/128, 256>>>(xyz, sidx, b1);
    k_layer2<<<ROWS/128, 256>>>(b2, g1, be1);
    k_layer3<<<ROWS/128, 256>>>(b3, g2, be2);
    k_apply<<<(BB*NPT*128)/256, 256>>>(g3, be3, outp);
}

// round 15
// speedup vs baseline: 1.3209x; 1.3209x over previous
#include <cuda_runtime.h>

#define BB 8
#define NN 16384
#define NPT 2048
#define NS 32
#define ROWS (BB*NPT*NS)   /* 524288 */
#define EPSV 1e-5f
#define INV_ROWS (1.0f/524288.0f)
#define WPAD 68            /* u64 row stride: 2*68 % 32 == 8 -> conflict-free LDS.64 */

typedef unsigned long long ull;
typedef unsigned int u32;

// ---------------- static device scratch ----------------
__device__ float4 g_pxyz[BB*NN];                       // packed (x,y,z,0.5*|p|^2)
__device__ float  g_ptst[(size_t)BB*NN*64];            // points transposed [b][n][c]
__device__ int    g_idx[BB*NPT*NS];                    // knn indices
__device__ float  g_h1[(size_t)ROWS*64];               // pre-BN layer1 out
__device__ float  g_h2[(size_t)ROWS*64];               // pre-BN layer2 out
__device__ float  g_mx[BB*NPT*128];                    // pre-BN pooled max
__device__ float  g_mn[BB*NPT*128];                    // pre-BN pooled min
__device__ float  g_stats[512];                        // S1 Q1 S2 Q2 S3[128] Q3[128]
__device__ ull    g_w1p[36*64];                        // paired hi-tf32 (b0,b1) [r][n]
__device__ ull    g_w2p[32*64];
__device__ ull    g_w3p[32*128];

// ---------------- tf32 helpers ----------------
__device__ __forceinline__ u32 f2tf32(float f) {
    u32 r;
    asm("cvt.rna.tf32.f32 %0, %1;" : "=r"(r) : "f"(f));
    return r;
}
__device__ __forceinline__ void tf32_split(float f, u32& hi, u32& lo) {
    hi = f2tf32(f);
    lo = f2tf32(f - __uint_as_float(hi));
}
__device__ __forceinline__ void mma_tf32(float& d0, float& d1, float& d2, float& d3,
                                         u32 a0, u32 a1, u32 a2, u32 a3,
                                         u32 b0, u32 b1) {
    asm volatile(
        "mma.sync.aligned.m16n8k8.row.col.f32.tf32.tf32.f32 "
        "{%0,%1,%2,%3}, {%4,%5,%6,%7}, {%8,%9}, {%0,%1,%2,%3};\n"
        : "+f"(d0), "+f"(d1), "+f"(d2), "+f"(d3)
        : "r"(a0), "r"(a1), "r"(a2), "r"(a3), "r"(b0), "r"(b1));
}

// ---------------- prep: stats zero + pxyz pack + gatherq + weight pair-pack ----------
__global__ void k_prep(const float* __restrict__ xyz,
                       const int* __restrict__ sidx,
                       const float* __restrict__ W1, const float* __restrict__ W2,
                       const float* __restrict__ W3, float* __restrict__ outq) {
    int i = blockIdx.x*256 + threadIdx.x;
    if (i < 512) g_stats[i] = 0.0f;
    if (i < BB*3*NPT) {
        int p = i & (NPT-1);
        int bc = i >> 11;
        outq[i] = xyz[bc*NN + sidx[p]];
    }
    if (i < BB*NN) {
        int b = i >> 14, n = i & (NN-1);
        float x = xyz[(b*3+0)*NN + n];
        float y = xyz[(b*3+1)*NN + n];
        float z = xyz[(b*3+2)*NN + n];
        g_pxyz[i] = make_float4(x, y, z, 0.5f*(x*x + y*y + z*z));
    } else {
        int wi = i - BB*NN;
        if (wi < 36*64) {
            int r = wi >> 6, n = wi & 63;
            int k = r >> 2, c = r & 3;
            int kk0 = 8*k + c, kk1 = kk0 + 4;
            float w0 = 0.0f, w1 = 0.0f;
            if (kk0 < 64)      w0 = W1[n*67 + 3 + kk0];
            else if (kk0 < 67) w0 = W1[n*67 + (kk0 - 64)];
            if (kk1 < 64)      w1 = W1[n*67 + 3 + kk1];
            else if (kk1 < 67) w1 = W1[n*67 + (kk1 - 64)];
            g_w1p[wi] = ((ull)f2tf32(w1) << 32) | f2tf32(w0);
        } else if (wi < 36*64 + 32*64) {
            int j = wi - 36*64;
            int r = j >> 6, n = j & 63;
            int k = r >> 2, c = r & 3;
            g_w2p[j] = ((ull)f2tf32(W2[n*64 + 8*k + c + 4]) << 32)
                     | f2tf32(W2[n*64 + 8*k + c]);
        } else if (wi < 36*64 + 32*64 + 32*128) {
            int j = wi - 36*64 - 32*64;
            int r = j >> 7, n = j & 127;
            int k = r >> 2, c = r & 3;
            g_w3p[j] = ((ull)f2tf32(W3[n*64 + 8*k + c + 4]) << 32)
                     | f2tf32(W3[n*64 + 8*k + c]);
        }
    }
}

// ---------------- tiled transpose points (B,C,N) -> (B,N,C), coalesced both ways ----
__global__ __launch_bounds__(256) void k_xpose(const float* __restrict__ pts) {
    __shared__ float tile[64*129];
    int blk = blockIdx.x;
    int b = blk >> 7;
    int nbase = (blk & 127) * 128;
    int tid = threadIdx.x;
    int nl = tid & 127, rh = tid >> 7;
    #pragma unroll
    for (int pass = 0; pass < 32; ++pass) {
        int row = rh + pass*2;
        tile[row*129 + nl] = pts[((size_t)(b*64 + row))*NN + nbase + nl];
    }
    __syncthreads();
    int cg = (tid & 15) * 4, nh = tid >> 4;
    #pragma unroll
    for (int pass = 0; pass < 8; ++pass) {
        int n = nh + pass*16;
        float4 v = make_float4(tile[cg*129 + n], tile[(cg+1)*129 + n],
                               tile[(cg+2)*129 + n], tile[(cg+3)*129 + n]);
        *(float4*)&g_ptst[((size_t)(b*NN + nbase + n))*64 + cg] = v;
    }
}

// ---------------- warp 64-bit shuffles ----------------
__device__ __forceinline__ ull shfl_xor_u64(ull v, int m) {
    u32 lo = (u32)v, hi = (u32)(v >> 32);
    lo = __shfl_xor_sync(0xffffffffu, lo, m);
    hi = __shfl_xor_sync(0xffffffffu, hi, m);
    return ((ull)hi << 32) | lo;
}
__device__ __forceinline__ ull shfl_idx_u64(ull v, int src) {
    u32 lo = (u32)v, hi = (u32)(v >> 32);
    lo = __shfl_sync(0xffffffffu, lo, src);
    hi = __shfl_sync(0xffffffffu, hi, src);
    return ((ull)hi << 32) | lo;
}

// ---------------- bitonic sort of 32 ull (1/lane), ascending ----------------
__device__ __forceinline__ ull bitonic_sort32(ull v, int lane) {
    #pragma unroll
    for (int k = 2; k <= 32; k <<= 1) {
        #pragma unroll
        for (int j = k >> 1; j > 0; j >>= 1) {
            ull o = shfl_xor_u64(v, j);
            bool lower  = (lane & j) == 0;
            bool dirUp  = (lane & k) == 0;
            bool takeMin = (lower == dirUp);
            bool sw = takeMin ? (o < v) : (o > v);
            v = sw ? o : v;
        }
    }
    return v;
}

// ---------------- knn flush: bitonic top-32 merge of buffered candidates ----------
__device__ __forceinline__ void knn_flush(ull& top, int& cnt, float& thr,
                                          ull* cb, int lane) {
    for (int base = 0; base < cnt; base += 32) {
        int idx = base + lane;
        ull s = (idx < cnt) ? cb[idx] : ~0ull;
        s = bitonic_sort32(s, lane);                 // ascending
        ull r = shfl_idx_u64(s, 31 - lane);          // descending
        ull m = (top < r) ? top : r;                 // bitonic; holds 32 smallest
        #pragma unroll
        for (int j = 16; j > 0; j >>= 1) {           // clean -> ascending
            ull o = shfl_xor_u64(m, j);
            bool lower = (lane & j) == 0;
            bool sw = lower ? (o < m) : (o > m);
            m = sw ? o : m;
        }
        top = m;
    }
    cnt = 0;
    ull k31 = shfl_idx_u64(top, 31);
    unsigned u = (unsigned)(k31 >> 32);
    float t;
    if (u == 0xFFFFFFFFu) {
        t = __int_as_float(0x7F800000);  // +inf
    } else {
        unsigned bits = (u & 0x80000000u) ? (u & 0x7FFFFFFFu) : ~u;
        t = __uint_as_float(bits);
    }
    thr = t;
}

__device__ __forceinline__ unsigned mono_map(float v) {
    unsigned u = __float_as_uint(v);
    return (u & 0x80000000u) ? ~u : (u | 0x80000000u);
}

// ---------------- knn: 16 queries/block (2 per warp), smem point tiles ----------------
__global__ __launch_bounds__(256) void k_knn(const float* __restrict__ xyz,
                                             const int* __restrict__ sidx) {
    __shared__ float4 sp[1024];                       // 16KB
    __shared__ ull cbuf[16*128];                      // 16KB
    int tid = threadIdx.x, lane = tid & 31, w = tid >> 5;
    int b = blockIdx.y;
    unsigned lml = (1u << lane) - 1u;
    ull* cb0 = &cbuf[(w*2+0)*128];
    ull* cb1 = &cbuf[(w*2+1)*128];

    int qg = blockIdx.x*16 + w*2;
    int s0 = sidx[qg], s1 = sidx[qg+1];
    float qx0 = xyz[(b*3+0)*NN + s0], qy0 = xyz[(b*3+1)*NN + s0], qz0 = xyz[(b*3+2)*NN + s0];
    float qx1 = xyz[(b*3+0)*NN + s1], qy1 = xyz[(b*3+1)*NN + s1], qz1 = xyz[(b*3+2)*NN + s1];
    float c20 = 0.5f*(qx0*qx0 + qy0*qy0 + qz0*qz0);
    float c21 = 0.5f*(qx1*qx1 + qy1*qy1 + qz1*qz1);
    const float INFF = __int_as_float(0x7F800000);
    ull top0 = ~0ull, top1 = ~0ull;
    float thr0 = INFF, thr1 = INFF;
    float u0 = INFF, u1 = INFF;
    int c0 = 0, c1 = 0;

    for (int t = 0; t < NN; t += 1024) {
        __syncthreads();
        #pragma unroll
        for (int j = 0; j < 4; ++j)
            sp[tid + j*256] = g_pxyz[b*NN + t + tid + j*256];
        __syncthreads();
        for (int jj = 0; jj < 1024; jj += 64) {
            if ((c0 | c1) > 64) {      // warp-uniform; appends <=64 per group
                if (c0 > 64) { knn_flush(top0, c0, thr0, cb0, lane); u0 = __fadd_ru(thr0, -c20); }
                if (c1 > 64) { knn_flush(top1, c1, thr1, cb1, lane); u1 = __fadd_ru(thr1, -c21); }
            }
            #pragma unroll
            for (int h = 0; h < 2; ++h) {
                int j = jj + h*32 + lane;
                float4 p = sp[j];
                float d0 = __fmaf_rn(-qx0, p.x, p.w);
                d0 = __fmaf_rn(-qy0, p.y, d0);
                d0 = __fmaf_rn(-qz0, p.z, d0);
                float d1 = __fmaf_rn(-qx1, p.x, p.w);
                d1 = __fmaf_rn(-qy1, p.y, d1);
                d1 = __fmaf_rn(-qz1, p.z, d1);
                bool pr0 = d0 < u0;
                bool pr1 = d1 < u1;
                if (__any_sync(0xffffffffu, pr0 || pr1)) {
                    unsigned m0 = __ballot_sync(0xffffffffu, pr0);
                    unsigned m1 = __ballot_sync(0xffffffffu, pr1);
                    if (pr0) {
                        unsigned ub = mono_map(d0 + c20);
                        cb0[c0 + __popc(m0 & lml)] = ((ull)ub << 32) | (unsigned)(t + j);
                    }
                    if (pr1) {
                        unsigned ub = mono_map(d1 + c21);
                        cb1[c1 + __popc(m1 & lml)] = ((ull)ub << 32) | (unsigned)(t + j);
                    }
                    c0 += __popc(m0);
                    c1 += __popc(m1);
                }
            }
        }
    }
    knn_flush(top0, c0, thr0, cb0, lane);
    knn_flush(top1, c1, thr1, cb1, lane);
    g_idx[(b*NPT + qg + 0)*NS + lane] = (int)(top0 & 0xffffffffu);
    g_idx[(b*NPT + qg + 1)*NS + lane] = (int)(top1 & 0xffffffffu);
}

// ============================================================================
// Layer kernels: k-OUTER loop, in-place accumulation into acc[8][4] (32 regs).
// A fragments are transient per k-step -> low regs -> 3 blocks/SM.
// Block = 256 threads = 8 warps; tile = 128 rows (4 complete centroids).
// ============================================================================

#define LAYER_STATS_EPI(d0,d1,d2,d3,hout,stride,ooff,nn8)                         \
    do {                                                                          \
        *(float2*)&hout[row0*stride + ooff + (nn8)*8 + 2*c] = make_float2(d0, d1);\
        *(float2*)&hout[row1*stride + ooff + (nn8)*8 + 2*c] = make_float2(d2, d3);\
        float s0 = d0 + d2, s1 = d1 + d3;                                         \
        float q0 = d0*d0 + d2*d2, q1 = d1*d1 + d3*d3;                             \
        _Pragma("unroll")                                                         \
        for (int m = 4; m <= 16; m <<= 1) {                                       \
            s0 += __shfl_xor_sync(0xffffffffu, s0, m);                            \
            s1 += __shfl_xor_sync(0xffffffffu, s1, m);                            \
            q0 += __shfl_xor_sync(0xffffffffu, q0, m);                            \
            q1 += __shfl_xor_sync(0xffffffffu, q1, m);                            \
        }                                                                         \
        if (lane < 4) {                                                           \
            int col0 = (nn8)*8 + 2*c;                                             \
            sm_s[w*64 + col0] = s0; sm_s[w*64 + col0 + 1] = s1;                   \
            sm_q[w*64 + col0] = q0; sm_q[w*64 + col0 + 1] = q1;                   \
        }                                                                         \
    } while (0)

__global__ __launch_bounds__(256, 3) void k_layer1(const float* __restrict__ xyz,
                                                   const int* __restrict__ sidx,
                                                   const float* __restrict__ b1) {
    __shared__ ull ws64[36*WPAD];
    __shared__ float bs[64];
    __shared__ float sm_s[512], sm_q[512];
    int tid = threadIdx.x;
    for (int i = tid; i < 36*64; i += 256)
        ws64[(i >> 6)*WPAD + (i & 63)] = g_w1p[i];
    if (tid < 64) bs[tid] = b1[tid];
    __syncthreads();

    int lane = tid & 31, w = tid >> 5;
    int g = lane >> 2, c = lane & 3;
    size_t row0 = (size_t)blockIdx.x*128 + w*16 + g;
    size_t row1 = row0 + 8;
    int b = (int)(row0 >> 16);
    int n0 = g_idx[row0], n1 = g_idx[row1];
    int p0 = ((int)row0 >> 5) & (NPT-1);
    int s = sidx[p0];
    float qx = xyz[(b*3+0)*NN + s], qy = xyz[(b*3+1)*NN + s], qz = xyz[(b*3+2)*NN + s];
    float4 P0 = g_pxyz[b*NN + n0];
    float4 P1 = g_pxyz[b*NN + n1];
    const float* f0 = &g_ptst[(size_t)(b*NN + n0)*64];
    const float* f1 = &g_ptst[(size_t)(b*NN + n1)*64];

    float acc[8][4];
    #pragma unroll
    for (int n8 = 0; n8 < 8; ++n8) {
        acc[n8][0] = bs[n8*8 + 2*c]; acc[n8][1] = bs[n8*8 + 2*c + 1];
        acc[n8][2] = acc[n8][0];     acc[n8][3] = acc[n8][1];
    }

    const ull* pb = &ws64[c*WPAD + g];
    #pragma unroll
    for (int k = 0; k < 9; ++k) {
        u32 a0h, a0l, a1h, a1l, a2h, a2l, a3h, a3l;
        if (k < 8) {
            int col0 = c + 8*k, col1 = col0 + 4;
            float x00 = __ldg(&f0[col0]);
            float x10 = __ldg(&f1[col0]);
            float x01 = __ldg(&f0[col1]);
            float x11 = __ldg(&f1[col1]);
            tf32_split(x00, a0h, a0l);
            tf32_split(x10, a1h, a1l);
            tf32_split(x01, a2h, a2l);
            tf32_split(x11, a3h, a3l);
        } else {
            float e0 = (c == 0) ? (P0.x - qx) : (c == 1) ? (P0.y - qy) : (c == 2) ? (P0.z - qz) : 0.0f;
            float e1 = (c == 0) ? (P1.x - qx) : (c == 1) ? (P1.y - qy) : (c == 2) ? (P1.z - qz) : 0.0f;
            tf32_split(e0, a0h, a0l);
            tf32_split(e1, a1h, a1l);
            a2h = 0; a2l = 0; a3h = 0; a3l = 0;
        }
        #pragma unroll
        for (int n8 = 0; n8 < 8; ++n8) {
            ull wv = pb[k*4*WPAD + n8*8];
            u32 b0 = (u32)wv, b1v = (u32)(wv >> 32);
            mma_tf32(acc[n8][0],acc[n8][1],acc[n8][2],acc[n8][3], a0h,a1h,a2h,a3h, b0,b1v);
            mma_tf32(acc[n8][0],acc[n8][1],acc[n8][2],acc[n8][3], a0l,a1l,a2l,a3l, b0,b1v);
        }
    }
    #pragma unroll
    for (int n8 = 0; n8 < 8; ++n8)
        LAYER_STATS_EPI(acc[n8][0],acc[n8][1],acc[n8][2],acc[n8][3], g_h1, 64, 0, n8);
    __syncthreads();
    if (tid < 64) {
        float S = 0.0f, Q = 0.0f;
        #pragma unroll
        for (int ww = 0; ww < 8; ++ww) { S += sm_s[ww*64 + tid]; Q += sm_q[ww*64 + tid]; }
        atomicAdd(&g_stats[tid], S);
        atomicAdd(&g_stats[64 + tid], Q);
    }
}

__global__ __launch_bounds__(256, 3) void k_layer2(const float* __restrict__ b2,
                                                   const float* __restrict__ g1,
                                                   const float* __restrict__ be1) {
    __shared__ ull ws64[32*WPAD];
    __shared__ float bs[64], sc[64], sh[64];
    __shared__ float sm_s[512], sm_q[512];
    int tid = threadIdx.x;
    for (int i = tid; i < 32*64; i += 256)
        ws64[(i >> 6)*WPAD + (i & 63)] = g_w2p[i];
    if (tid < 64) {
        bs[tid] = b2[tid];
        float m = g_stats[tid] * INV_ROWS;
        float v = g_stats[64+tid] * INV_ROWS - m*m;
        float scv = g1[tid] * rsqrtf(v + EPSV);
        sc[tid] = scv;
        sh[tid] = be1[tid] - m*scv;
    }
    __syncthreads();

    int lane = tid & 31, w = tid >> 5;
    int g = lane >> 2, c = lane & 3;
    size_t row0 = (size_t)blockIdx.x*128 + w*16 + g;
    size_t row1 = row0 + 8;
    const float* h0 = &g_h1[row0*64];
    const float* h1p = &g_h1[row1*64];

    float acc[8][4];
    #pragma unroll
    for (int n8 = 0; n8 < 8; ++n8) {
        acc[n8][0] = bs[n8*8 + 2*c]; acc[n8][1] = bs[n8*8 + 2*c + 1];
        acc[n8][2] = acc[n8][0];     acc[n8][3] = acc[n8][1];
    }

    const ull* pb = &ws64[c*WPAD + g];
    #pragma unroll
    for (int k = 0; k < 8; ++k) {
        int col0 = c + 8*k, col1 = col0 + 4;
        float sc0 = sc[col0], sh0 = sh[col0];
        float sc1 = sc[col1], sh1 = sh[col1];
        float x00 = fmaxf(__ldg(&h0[col0])*sc0 + sh0, 0.0f);
        float x10 = fmaxf(__ldg(&h1p[col0])*sc0 + sh0, 0.0f);
        float x01 = fmaxf(__ldg(&h0[col1])*sc1 + sh1, 0.0f);
        float x11 = fmaxf(__ldg(&h1p[col1])*sc1 + sh1, 0.0f);
        u32 a0h, a0l, a1h, a1l, a2h, a2l, a3h, a3l;
        tf32_split(x00, a0h, a0l);
        tf32_split(x10, a1h, a1l);
        tf32_split(x01, a2h, a2l);
        tf32_split(x11, a3h, a3l);
        #pragma unroll
        for (int n8 = 0; n8 < 8; ++n8) {
            ull wv = pb[k*4*WPAD + n8*8];
            u32 b0 = (u32)wv, b1v = (u32)(wv >> 32);
            mma_tf32(acc[n8][0],acc[n8][1],acc[n8][2],acc[n8][3], a0h,a1h,a2h,a3h, b0,b1v);
            mma_tf32(acc[n8][0],acc[n8][1],acc[n8][2],acc[n8][3], a0l,a1l,a2l,a3l, b0,b1v);
        }
    }
    #pragma unroll
    for (int n8 = 0; n8 < 8; ++n8)
        LAYER_STATS_EPI(acc[n8][0],acc[n8][1],acc[n8][2],acc[n8][3], g_h2, 64, 0, n8);
    __syncthreads();
    if (tid < 64) {
        float S = 0.0f, Q = 0.0f;
        #pragma unroll
        for (int ww = 0; ww < 8; ++ww) { S += sm_s[ww*64 + tid]; Q += sm_q[ww*64 + tid]; }
        atomicAdd(&g_stats[128 + tid], S);
        atomicAdd(&g_stats[192 + tid], Q);
    }
}

#define POOL_EPI(d0,d1,d2,d3,nn8)                                                 \
    do {                                                                          \
        float mx0 = fmaxf(d0, d2), mn0 = fminf(d0, d2);                           \
        float mx1 = fmaxf(d1, d3), mn1 = fminf(d1, d3);                           \
        float s0 = d0 + d2, s1 = d1 + d3;                                         \
        float q0 = d0*d0 + d2*d2, q1 = d1*d1 + d3*d3;                             \
        _Pragma("unroll")                                                         \
        for (int m = 4; m <= 16; m <<= 1) {                                       \
            mx0 = fmaxf(mx0, __shfl_xor_sync(0xffffffffu, mx0, m));               \
            mn0 = fminf(mn0, __shfl_xor_sync(0xffffffffu, mn0, m));               \
            mx1 = fmaxf(mx1, __shfl_xor_sync(0xffffffffu, mx1, m));               \
            mn1 = fminf(mn1, __shfl_xor_sync(0xffffffffu, mn1, m));               \
            s0 += __shfl_xor_sync(0xffffffffu, s0, m);                            \
            s1 += __shfl_xor_sync(0xffffffffu, s1, m);                            \
            q0 += __shfl_xor_sync(0xffffffffu, q0, m);                            \
            q1 += __shfl_xor_sync(0xffffffffu, q1, m);                            \
        }                                                                         \
        if (lane < 4) {                                                           \
            int col0 = (nn8)*8 + 2*c;                                             \
            sm_mx[w*64 + col0] = mx0; sm_mx[w*64 + col0 + 1] = mx1;               \
            sm_mn[w*64 + col0] = mn0; sm_mn[w*64 + col0 + 1] = mn1;               \
            sm_s[w*64 + col0] = s0;   sm_s[w*64 + col0 + 1] = s1;                 \
            sm_q[w*64 + col0] = q0;   sm_q[w*64 + col0 + 1] = q1;                 \
        }                                                                         \
    } while (0)

__global__ __launch_bounds__(256, 3) void k_layer3(const float* __restrict__ b3,
                                                   const float* __restrict__ g2,
                                                   const float* __restrict__ be2) {
    __shared__ ull ws64[64*WPAD];
    __shared__ float bs[128], sc[64], sh[64];
    __shared__ float sm_mx[512], sm_mn[512], sm_s[512], sm_q[512];
    int tid = threadIdx.x;
    int lane = tid & 31, w = tid >> 5;
    int g = lane >> 2, c = lane & 3;

    for (int i = tid; i < 32*128; i += 256) {
        int r = i >> 7, n = i & 127;
        ws64[(n >> 6)*32*WPAD + r*WPAD + (n & 63)] = g_w3p[i];
    }
    if (tid < 128) bs[tid] = b3[tid];
    if (tid < 64) {
        float m = g_stats[128+tid] * INV_ROWS;
        float v = g_stats[192+tid] * INV_ROWS - m*m;
        float scv = g2[tid] * rsqrtf(v + EPSV);
        sc[tid] = scv;
        sh[tid] = be2[tid] - m*scv;
    }
    __syncthreads();

    size_t row0 = (size_t)blockIdx.x*128 + w*16 + g;
    size_t row1 = row0 + 8;
    const float* h0 = &g_h2[row0*64];
    const float* h1p = &g_h2[row1*64];

    #pragma unroll
    for (int oh = 0; oh < 2; ++oh) {
        if (oh == 1) __syncthreads();
        const ull* pb = &ws64[oh*32*WPAD + c*WPAD + g];
        float acc[8][4];
        #pragma unroll
        for (int n8 = 0; n8 < 8; ++n8) {
            acc[n8][0] = bs[oh*64 + n8*8 + 2*c]; acc[n8][1] = bs[oh*64 + n8*8 + 2*c + 1];
            acc[n8][2] = acc[n8][0];             acc[n8][3] = acc[n8][1];
        }
        #pragma unroll
        for (int k = 0; k < 8; ++k) {
            int col0 = c + 8*k, col1 = col0 + 4;
            float sc0 = sc[col0], sh0 = sh[col0];
            float sc1 = sc[col1], sh1 = sh[col1];
            float x00 = fmaxf(__ldg(&h0[col0])*sc0 + sh0, 0.0f);
            float x10 = fmaxf(__ldg(&h1p[col0])*sc0 + sh0, 0.0f);
            float x01 = fmaxf(__ldg(&h0[col1])*sc1 + sh1, 0.0f);
            float x11 = fmaxf(__ldg(&h1p[col1])*sc1 + sh1, 0.0f);
            u32 a0h, a0l, a1h, a1l, a2h, a2l, a3h, a3l;
            tf32_split(x00, a0h, a0l);
            tf32_split(x10, a1h, a1l);
            tf32_split(x01, a2h, a2l);
            tf32_split(x11, a3h, a3l);
            #pragma unroll
            for (int n8 = 0; n8 < 8; ++n8) {
                ull wv = pb[k*4*WPAD + n8*8];
                u32 b0 = (u32)wv, b1v = (u32)(wv >> 32);
                mma_tf32(acc[n8][0],acc[n8][1],acc[n8][2],acc[n8][3], a0h,a1h,a2h,a3h, b0,b1v);
                mma_tf32(acc[n8][0],acc[n8][1],acc[n8][2],acc[n8][3], a0l,a1l,a2l,a3l, b0,b1v);
            }
        }
        #pragma unroll
        for (int n8 = 0; n8 < 8; ++n8)
            POOL_EPI(acc[n8][0],acc[n8][1],acc[n8][2],acc[n8][3], n8);
        __syncthreads();
        {
            int ct = tid >> 6, col = tid & 63;
            float mx = fmaxf(sm_mx[(2*ct)*64 + col], sm_mx[(2*ct+1)*64 + col]);
            float mn = fminf(sm_mn[(2*ct)*64 + col], sm_mn[(2*ct+1)*64 + col]);
            size_t bpos = (size_t)blockIdx.x*4 + ct;
            g_mx[bpos*128 + oh*64 + col] = mx;
            g_mn[bpos*128 + oh*64 + col] = mn;
            if (tid < 64) {
                float S = 0.0f, Q = 0.0f;
                #pragma unroll
                for (int ww = 0; ww < 8; ++ww) { S += sm_s[ww*64 + tid]; Q += sm_q[ww*64 + tid]; }
                atomicAdd(&g_stats[256 + oh*64 + tid], S);
                atomicAdd(&g_stats[384 + oh*64 + tid], Q);
            }
        }
    }
}

// ---------------- apply BN3 affine to pooled max/min, transpose-store ----------------
__global__ __launch_bounds__(256) void k_apply(const float* __restrict__ g3,
                                               const float* __restrict__ be3,
                                               float* __restrict__ outp) {
    int i = blockIdx.x*256 + threadIdx.x;      // 16384*128
    int c = i & 127;
    int bp = i >> 7;
    int b = bp >> 11, p = bp & (NPT-1);
    float m = g_stats[256+c] * INV_ROWS;
    float v = g_stats[384+c] * INV_ROWS - m*m;
    float scv = g3[c] * rsqrtf(v + EPSV);
    float sh = be3[c] - m*scv;
    float pick = (scv >= 0.0f) ? g_mx[i] : g_mn[i];
    outp[((size_t)b*128 + c)*NPT + p] = pick*scv + sh;
}

// ---------------- launch ----------------
extern "C" void kernel_launch(void* const* d_in, const int* in_sizes, int n_in,
                              void* d_out, int out_size) {
    const float* xyz    = (const float*)d_in[0];
    const float* points = (const float*)d_in[1];
    const int*   sidx   = (const int*)d_in[2];
    const float* W1 = (const float*)d_in[3];
    const float* b1 = (const float*)d_in[4];
    const float* g1 = (const float*)d_in[5];
    const float* be1 = (const float*)d_in[6];
    const float* W2 = (const float*)d_in[7];
    const float* b2 = (const float*)d_in[8];
    const float* g2 = (const float*)d_in[9];
    const float* be2 = (const float*)d_in[10];
    const float* W3 = (const float*)d_in[11];
    const float* b3 = (const float*)d_in[12];
    const float* g3 = (const float*)d_in[13];
    const float* be3 = (const float*)d_in[14];

    float* outq = (float*)d_out;                 // (B,3,NPT)
    float* outp = outq + (size_t)BB*3*NPT;       // (B,128,NPT)

    const int prep_total = BB*NN + 36*64 + 32*64 + 32*128;
    k_prep<<<(prep_total + 255)/256, 256>>>(xyz, sidx, W1, W2, W3, outq);
    k_xpose<<<BB*NN/128, 256>>>(points);
    k_knn<<<dim3(NPT/16, BB), 256>>>(xyz, sidx);
    k_layer1<<<ROWS/128, 256>>>(xyz, sidx, b1);
    k_layer2<<<ROWS/128, 256>>>(b2, g1, be1);
    k_layer3<<<ROWS/128, 256>>>(b3, g2, be2);
    k_apply<<<(BB*NPT*128)/256, 256>>>(g3, be3, outp);
}

// round 16
// speedup vs baseline: 1.4651x; 1.1092x over previous
#include <cuda_runtime.h>

#define BB 8
#define NN 16384
#define NPT 2048
#define NS 32
#define ROWS (BB*NPT*NS)   /* 524288 */
#define EPSV 1e-5f
#define INV_ROWS (1.0f/524288.0f)
#define WPAD 68            /* u64 row stride: 2*68 % 32 == 8 -> conflict-free LDS.64 */

typedef unsigned long long ull;
typedef unsigned int u32;

// ---------------- static device scratch ----------------
__device__ float4 g_pxyz[BB*NN];                       // packed (x,y,z,0.5*|p|^2)
__device__ float  g_ptst[(size_t)BB*NN*64];            // points transposed [b][n][c]
__device__ int    g_idx[BB*NPT*NS];                    // knn indices
__device__ float  g_h1[(size_t)ROWS*64];               // pre-BN layer1 out
__device__ float  g_h2[(size_t)ROWS*64];               // pre-BN layer2 out
__device__ float  g_mx[BB*NPT*128];                    // pre-BN pooled max
__device__ float  g_mn[BB*NPT*128];                    // pre-BN pooled min
__device__ float  g_stats[512];                        // S1 Q1 S2 Q2 S3[128] Q3[128]
__device__ ull    g_w1p[36*64];                        // paired hi-tf32 (b0,b1) [r][n]
__device__ ull    g_w2p[32*64];
__device__ ull    g_w3p[32*128];

// ---------------- tf32 helpers ----------------
__device__ __forceinline__ u32 f2tf32(float f) {
    u32 r;
    asm("cvt.rna.tf32.f32 %0, %1;" : "=r"(r) : "f"(f));
    return r;
}
__device__ __forceinline__ void tf32_split(float f, u32& hi, u32& lo) {
    hi = f2tf32(f);
    lo = f2tf32(f - __uint_as_float(hi));
}
__device__ __forceinline__ void mma_tf32(float& d0, float& d1, float& d2, float& d3,
                                         u32 a0, u32 a1, u32 a2, u32 a3,
                                         u32 b0, u32 b1) {
    asm volatile(
        "mma.sync.aligned.m16n8k8.row.col.f32.tf32.tf32.f32 "
        "{%0,%1,%2,%3}, {%4,%5,%6,%7}, {%8,%9}, {%0,%1,%2,%3};\n"
        : "+f"(d0), "+f"(d1), "+f"(d2), "+f"(d3)
        : "r"(a0), "r"(a1), "r"(a2), "r"(a3), "r"(b0), "r"(b1));
}

// ---------------- prep: stats zero + pxyz pack + gatherq + weight pair-pack ----------
__global__ void k_prep(const float* __restrict__ xyz,
                       const int* __restrict__ sidx,
                       const float* __restrict__ W1, const float* __restrict__ W2,
                       const float* __restrict__ W3, float* __restrict__ outq) {
    int i = blockIdx.x*256 + threadIdx.x;
    if (i < 512) g_stats[i] = 0.0f;
    if (i < BB*3*NPT) {
        int p = i & (NPT-1);
        int bc = i >> 11;
        outq[i] = xyz[bc*NN + sidx[p]];
    }
    if (i < BB*NN) {
        int b = i >> 14, n = i & (NN-1);
        float x = xyz[(b*3+0)*NN + n];
        float y = xyz[(b*3+1)*NN + n];
        float z = xyz[(b*3+2)*NN + n];
        g_pxyz[i] = make_float4(x, y, z, 0.5f*(x*x + y*y + z*z));
    } else {
        int wi = i - BB*NN;
        if (wi < 36*64) {
            int r = wi >> 6, n = wi & 63;
            int k = r >> 2, c = r & 3;
            int kk0 = 8*k + c, kk1 = kk0 + 4;
            float w0 = 0.0f, w1 = 0.0f;
            if (kk0 < 64)      w0 = W1[n*67 + 3 + kk0];
            else if (kk0 < 67) w0 = W1[n*67 + (kk0 - 64)];
            if (kk1 < 64)      w1 = W1[n*67 + 3 + kk1];
            else if (kk1 < 67) w1 = W1[n*67 + (kk1 - 64)];
            g_w1p[wi] = ((ull)f2tf32(w1) << 32) | f2tf32(w0);
        } else if (wi < 36*64 + 32*64) {
            int j = wi - 36*64;
            int r = j >> 6, n = j & 63;
            int k = r >> 2, c = r & 3;
            g_w2p[j] = ((ull)f2tf32(W2[n*64 + 8*k + c + 4]) << 32)
                     | f2tf32(W2[n*64 + 8*k + c]);
        } else if (wi < 36*64 + 32*64 + 32*128) {
            int j = wi - 36*64 - 32*64;
            int r = j >> 7, n = j & 127;
            int k = r >> 2, c = r & 3;
            g_w3p[j] = ((ull)f2tf32(W3[n*64 + 8*k + c + 4]) << 32)
                     | f2tf32(W3[n*64 + 8*k + c]);
        }
    }
}

// ---------------- tiled transpose points (B,C,N) -> (B,N,C), coalesced both ways ----
__global__ __launch_bounds__(256) void k_xpose(const float* __restrict__ pts) {
    __shared__ float tile[64*129];
    int blk = blockIdx.x;
    int b = blk >> 7;
    int nbase = (blk & 127) * 128;
    int tid = threadIdx.x;
    int nl = tid & 127, rh = tid >> 7;
    #pragma unroll
    for (int pass = 0; pass < 32; ++pass) {
        int row = rh + pass*2;
        tile[row*129 + nl] = pts[((size_t)(b*64 + row))*NN + nbase + nl];
    }
    __syncthreads();
    int cg = (tid & 15) * 4, nh = tid >> 4;
    #pragma unroll
    for (int pass = 0; pass < 8; ++pass) {
        int n = nh + pass*16;
        float4 v = make_float4(tile[cg*129 + n], tile[(cg+1)*129 + n],
                               tile[(cg+2)*129 + n], tile[(cg+3)*129 + n]);
        *(float4*)&g_ptst[((size_t)(b*NN + nbase + n))*64 + cg] = v;
    }
}

// ---------------- warp 64-bit shuffles ----------------
__device__ __forceinline__ ull shfl_xor_u64(ull v, int m) {
    u32 lo = (u32)v, hi = (u32)(v >> 32);
    lo = __shfl_xor_sync(0xffffffffu, lo, m);
    hi = __shfl_xor_sync(0xffffffffu, hi, m);
    return ((ull)hi << 32) | lo;
}
__device__ __forceinline__ ull shfl_idx_u64(ull v, int src) {
    u32 lo = (u32)v, hi = (u32)(v >> 32);
    lo = __shfl_sync(0xffffffffu, lo, src);
    hi = __shfl_sync(0xffffffffu, hi, src);
    return ((ull)hi << 32) | lo;
}

// ---------------- bitonic sort of 32 ull (1/lane), ascending ----------------
__device__ __forceinline__ ull bitonic_sort32(ull v, int lane) {
    #pragma unroll
    for (int k = 2; k <= 32; k <<= 1) {
        #pragma unroll
        for (int j = k >> 1; j > 0; j >>= 1) {
            ull o = shfl_xor_u64(v, j);
            bool lower  = (lane & j) == 0;
            bool dirUp  = (lane & k) == 0;
            bool takeMin = (lower == dirUp);
            bool sw = takeMin ? (o < v) : (o > v);
            v = sw ? o : v;
        }
    }
    return v;
}

// ---------------- knn flush: bitonic top-32 merge of buffered candidates ----------
__device__ __forceinline__ void knn_flush(ull& top, int& cnt, float& thr,
                                          ull* cb, int lane) {
    for (int base = 0; base < cnt; base += 32) {
        int idx = base + lane;
        ull s = (idx < cnt) ? cb[idx] : ~0ull;
        s = bitonic_sort32(s, lane);                 // ascending
        ull r = shfl_idx_u64(s, 31 - lane);          // descending
        ull m = (top < r) ? top : r;                 // bitonic; holds 32 smallest
        #pragma unroll
        for (int j = 16; j > 0; j >>= 1) {           // clean -> ascending
            ull o = shfl_xor_u64(m, j);
            bool lower = (lane & j) == 0;
            bool sw = lower ? (o < m) : (o > m);
            m = sw ? o : m;
        }
        top = m;
    }
    cnt = 0;
    ull k31 = shfl_idx_u64(top, 31);
    unsigned u = (unsigned)(k31 >> 32);
    float t;
    if (u == 0xFFFFFFFFu) {
        t = __int_as_float(0x7F800000);  // +inf
    } else {
        unsigned bits = (u & 0x80000000u) ? (u & 0x7FFFFFFFu) : ~u;
        t = __uint_as_float(bits);
    }
    thr = t;
}

__device__ __forceinline__ unsigned mono_map(float v) {
    unsigned u = __float_as_uint(v);
    return (u & 0x80000000u) ? ~u : (u | 0x80000000u);
}

// ---------------- knn: 16 queries/block (2 per warp), smem point tiles ----------------
__global__ __launch_bounds__(256) void k_knn(const float* __restrict__ xyz,
                                             const int* __restrict__ sidx) {
    __shared__ float4 sp[1024];                       // 16KB
    __shared__ ull cbuf[16*128];                      // 16KB
    int tid = threadIdx.x, lane = tid & 31, w = tid >> 5;
    int b = blockIdx.y;
    unsigned lml = (1u << lane) - 1u;
    ull* cb0 = &cbuf[(w*2+0)*128];
    ull* cb1 = &cbuf[(w*2+1)*128];

    int qg = blockIdx.x*16 + w*2;
    int s0 = sidx[qg], s1 = sidx[qg+1];
    float qx0 = xyz[(b*3+0)*NN + s0], qy0 = xyz[(b*3+1)*NN + s0], qz0 = xyz[(b*3+2)*NN + s0];
    float qx1 = xyz[(b*3+0)*NN + s1], qy1 = xyz[(b*3+1)*NN + s1], qz1 = xyz[(b*3+2)*NN + s1];
    float c20 = 0.5f*(qx0*qx0 + qy0*qy0 + qz0*qz0);
    float c21 = 0.5f*(qx1*qx1 + qy1*qy1 + qz1*qz1);
    const float INFF = __int_as_float(0x7F800000);
    ull top0 = ~0ull, top1 = ~0ull;
    float thr0 = INFF, thr1 = INFF;
    float u0 = INFF, u1 = INFF;
    int c0 = 0, c1 = 0;

    for (int t = 0; t < NN; t += 1024) {
        __syncthreads();
        #pragma unroll
        for (int j = 0; j < 4; ++j)
            sp[tid + j*256] = g_pxyz[b*NN + t + tid + j*256];
        __syncthreads();
        for (int jj = 0; jj < 1024; jj += 64) {
            if ((c0 | c1) > 64) {      // warp-uniform; appends <=64 per group
                if (c0 > 64) { knn_flush(top0, c0, thr0, cb0, lane); u0 = __fadd_ru(thr0, -c20); }
                if (c1 > 64) { knn_flush(top1, c1, thr1, cb1, lane); u1 = __fadd_ru(thr1, -c21); }
            }
            #pragma unroll
            for (int h = 0; h < 2; ++h) {
                int j = jj + h*32 + lane;
                float4 p = sp[j];
                float d0 = __fmaf_rn(-qx0, p.x, p.w);
                d0 = __fmaf_rn(-qy0, p.y, d0);
                d0 = __fmaf_rn(-qz0, p.z, d0);
                float d1 = __fmaf_rn(-qx1, p.x, p.w);
                d1 = __fmaf_rn(-qy1, p.y, d1);
                d1 = __fmaf_rn(-qz1, p.z, d1);
                bool pr0 = d0 < u0;
                bool pr1 = d1 < u1;
                if (__any_sync(0xffffffffu, pr0 || pr1)) {
                    unsigned m0 = __ballot_sync(0xffffffffu, pr0);
                    unsigned m1 = __ballot_sync(0xffffffffu, pr1);
                    if (pr0) {
                        unsigned ub = mono_map(d0 + c20);
                        cb0[c0 + __popc(m0 & lml)] = ((ull)ub << 32) | (unsigned)(t + j);
                    }
                    if (pr1) {
                        unsigned ub = mono_map(d1 + c21);
                        cb1[c1 + __popc(m1 & lml)] = ((ull)ub << 32) | (unsigned)(t + j);
                    }
                    c0 += __popc(m0);
                    c1 += __popc(m1);
                }
            }
        }
    }
    knn_flush(top0, c0, thr0, cb0, lane);
    knn_flush(top1, c1, thr1, cb1, lane);
    g_idx[(b*NPT + qg + 0)*NS + lane] = (int)(top0 & 0xffffffffu);
    g_idx[(b*NPT + qg + 1)*NS + lane] = (int)(top1 & 0xffffffffu);
}

// ============================================================================
// Layer kernels: k-OUTER, M=32 rows/warp (two 16-row MMA tiles share each
// B-fragment LDS.64) -> weight smem traffic per row halved.
// Block = 256 threads = 8 warps; tile = 256 rows (8 complete centroids).
// ============================================================================

// 4-row epilogue: store + stats reduce (rows r0, r0+8, r0+16, r0+24)
#define LAYER_STATS_EPI4(A, A2, hout, nn8)                                        \
    do {                                                                          \
        *(float2*)&hout[(r0     )*64 + (nn8)*8 + 2*c] = make_float2(A[nn8][0], A[nn8][1]); \
        *(float2*)&hout[(r0 +  8)*64 + (nn8)*8 + 2*c] = make_float2(A[nn8][2], A[nn8][3]); \
        *(float2*)&hout[(r0 + 16)*64 + (nn8)*8 + 2*c] = make_float2(A2[nn8][0], A2[nn8][1]); \
        *(float2*)&hout[(r0 + 24)*64 + (nn8)*8 + 2*c] = make_float2(A2[nn8][2], A2[nn8][3]); \
        float s0 = (A[nn8][0] + A[nn8][2]) + (A2[nn8][0] + A2[nn8][2]);           \
        float s1 = (A[nn8][1] + A[nn8][3]) + (A2[nn8][1] + A2[nn8][3]);           \
        float q0 = (A[nn8][0]*A[nn8][0] + A[nn8][2]*A[nn8][2])                    \
                 + (A2[nn8][0]*A2[nn8][0] + A2[nn8][2]*A2[nn8][2]);               \
        float q1 = (A[nn8][1]*A[nn8][1] + A[nn8][3]*A[nn8][3])                    \
                 + (A2[nn8][1]*A2[nn8][1] + A2[nn8][3]*A2[nn8][3]);               \
        _Pragma("unroll")                                                         \
        for (int m = 4; m <= 16; m <<= 1) {                                       \
            s0 += __shfl_xor_sync(0xffffffffu, s0, m);                            \
            s1 += __shfl_xor_sync(0xffffffffu, s1, m);                            \
            q0 += __shfl_xor_sync(0xffffffffu, q0, m);                            \
            q1 += __shfl_xor_sync(0xffffffffu, q1, m);                            \
        }                                                                         \
        if (lane < 4) {                                                           \
            int col0 = (nn8)*8 + 2*c;                                             \
            sm_s[w*64 + col0] = s0; sm_s[w*64 + col0 + 1] = s1;                   \
            sm_q[w*64 + col0] = q0; sm_q[w*64 + col0 + 1] = q1;                   \
        }                                                                         \
    } while (0)

// ---------------- layer1: feat(72 padded) @ W1^T + b1 -> g_h1 + stats ----------------
__global__ __launch_bounds__(256, 2) void k_layer1(const float* __restrict__ xyz,
                                                   const int* __restrict__ sidx,
                                                   const float* __restrict__ b1) {
    __shared__ ull ws64[36*WPAD];
    __shared__ float bs[64];
    __shared__ float sm_s[512], sm_q[512];
    int tid = threadIdx.x;
    for (int i = tid; i < 36*64; i += 256)
        ws64[(i >> 6)*WPAD + (i & 63)] = g_w1p[i];
    if (tid < 64) bs[tid] = b1[tid];
    __syncthreads();

    int lane = tid & 31, w = tid >> 5;
    int g = lane >> 2, c = lane & 3;
    size_t base = (size_t)blockIdx.x*256 + w*32;      // 32 consecutive rows = 1 centroid
    size_t r0 = base + g;
    int b = (int)(base >> 16);
    int p0 = ((int)base >> 5) & (NPT-1);
    int s = sidx[p0];
    float qx = xyz[(b*3+0)*NN + s], qy = xyz[(b*3+1)*NN + s], qz = xyz[(b*3+2)*NN + s];
    int nn[4];
    const float* f[4];
    float ex[4], ey[4], ez[4];
    #pragma unroll
    for (int j = 0; j < 4; ++j) {
        nn[j] = g_idx[r0 + j*8];
        float4 P = g_pxyz[b*NN + nn[j]];
        ex[j] = P.x - qx; ey[j] = P.y - qy; ez[j] = P.z - qz;
        f[j] = &g_ptst[(size_t)(b*NN + nn[j])*64];
    }

    float acc[8][4], acc2[8][4];
    #pragma unroll
    for (int n8 = 0; n8 < 8; ++n8) {
        float b0v = bs[n8*8 + 2*c], b1v = bs[n8*8 + 2*c + 1];
        acc[n8][0] = b0v; acc[n8][1] = b1v; acc[n8][2] = b0v; acc[n8][3] = b1v;
        acc2[n8][0] = b0v; acc2[n8][1] = b1v; acc2[n8][2] = b0v; acc2[n8][3] = b1v;
    }

    const ull* pb = &ws64[c*WPAD + g];
    #pragma unroll
    for (int k = 0; k < 9; ++k) {
        u32 ah[8], al[8];
        if (k < 8) {
            int col0 = c + 8*k, col1 = col0 + 4;
            tf32_split(__ldg(&f[0][col0]), ah[0], al[0]);
            tf32_split(__ldg(&f[1][col0]), ah[1], al[1]);
            tf32_split(__ldg(&f[0][col1]), ah[2], al[2]);
            tf32_split(__ldg(&f[1][col1]), ah[3], al[3]);
            tf32_split(__ldg(&f[2][col0]), ah[4], al[4]);
            tf32_split(__ldg(&f[3][col0]), ah[5], al[5]);
            tf32_split(__ldg(&f[2][col1]), ah[6], al[6]);
            tf32_split(__ldg(&f[3][col1]), ah[7], al[7]);
        } else {
            #pragma unroll
            for (int j = 0; j < 4; ++j) {
                float e = (c == 0) ? ex[j] : (c == 1) ? ey[j] : (c == 2) ? ez[j] : 0.0f;
                int slot = (j < 2) ? j : (2 + j);    // j=0,1 -> 0,1 ; j=2,3 -> 4,5
                tf32_split(e, ah[slot], al[slot]);
            }
            ah[2] = 0; al[2] = 0; ah[3] = 0; al[3] = 0;
            ah[6] = 0; al[6] = 0; ah[7] = 0; al[7] = 0;
        }
        #pragma unroll
        for (int n8 = 0; n8 < 8; ++n8) {
            ull wv = pb[k*4*WPAD + n8*8];
            u32 b0 = (u32)wv, b1v = (u32)(wv >> 32);
            mma_tf32(acc[n8][0],acc[n8][1],acc[n8][2],acc[n8][3],  ah[0],ah[1],ah[2],ah[3], b0,b1v);
            mma_tf32(acc2[n8][0],acc2[n8][1],acc2[n8][2],acc2[n8][3], ah[4],ah[5],ah[6],ah[7], b0,b1v);
            mma_tf32(acc[n8][0],acc[n8][1],acc[n8][2],acc[n8][3],  al[0],al[1],al[2],al[3], b0,b1v);
            mma_tf32(acc2[n8][0],acc2[n8][1],acc2[n8][2],acc2[n8][3], al[4],al[5],al[6],al[7], b0,b1v);
        }
    }
    #pragma unroll
    for (int n8 = 0; n8 < 8; ++n8)
        LAYER_STATS_EPI4(acc, acc2, g_h1, n8);
    __syncthreads();
    if (tid < 64) {
        float S = 0.0f, Q = 0.0f;
        #pragma unroll
        for (int ww = 0; ww < 8; ++ww) { S += sm_s[ww*64 + tid]; Q += sm_q[ww*64 + tid]; }
        atomicAdd(&g_stats[tid], S);
        atomicAdd(&g_stats[64 + tid], Q);
    }
}

// ---------------- layer2: relu(BN1(h1)) @ W2^T + b2 -> g_h2 + stats ----------------
__global__ __launch_bounds__(256, 2) void k_layer2(const float* __restrict__ b2,
                                                   const float* __restrict__ g1,
                                                   const float* __restrict__ be1) {
    __shared__ ull ws64[32*WPAD];
    __shared__ float bs[64], sc[64], sh[64];
    __shared__ float sm_s[512], sm_q[512];
    int tid = threadIdx.x;
    for (int i = tid; i < 32*64; i += 256)
        ws64[(i >> 6)*WPAD + (i & 63)] = g_w2p[i];
    if (tid < 64) {
        bs[tid] = b2[tid];
        float m = g_stats[tid] * INV_ROWS;
        float v = g_stats[64+tid] * INV_ROWS - m*m;
        float scv = g1[tid] * rsqrtf(v + EPSV);
        sc[tid] = scv;
        sh[tid] = be1[tid] - m*scv;
    }
    __syncthreads();

    int lane = tid & 31, w = tid >> 5;
    int g = lane >> 2, c = lane & 3;
    size_t base = (size_t)blockIdx.x*256 + w*32;
    size_t r0 = base + g;
    const float* h[4];
    #pragma unroll
    for (int j = 0; j < 4; ++j) h[j] = &g_h1[(r0 + j*8)*64];

    float acc[8][4], acc2[8][4];
    #pragma unroll
    for (int n8 = 0; n8 < 8; ++n8) {
        float b0v = bs[n8*8 + 2*c], b1v = bs[n8*8 + 2*c + 1];
        acc[n8][0] = b0v; acc[n8][1] = b1v; acc[n8][2] = b0v; acc[n8][3] = b1v;
        acc2[n8][0] = b0v; acc2[n8][1] = b1v; acc2[n8][2] = b0v; acc2[n8][3] = b1v;
    }

    const ull* pb = &ws64[c*WPAD + g];
    #pragma unroll
    for (int k = 0; k < 8; ++k) {
        int col0 = c + 8*k, col1 = col0 + 4;
        float sc0 = sc[col0], sh0 = sh[col0];
        float sc1 = sc[col1], sh1 = sh[col1];
        u32 ah[8], al[8];
        tf32_split(fmaxf(__ldg(&h[0][col0])*sc0 + sh0, 0.0f), ah[0], al[0]);
        tf32_split(fmaxf(__ldg(&h[1][col0])*sc0 + sh0, 0.0f), ah[1], al[1]);
        tf32_split(fmaxf(__ldg(&h[0][col1])*sc1 + sh1, 0.0f), ah[2], al[2]);
        tf32_split(fmaxf(__ldg(&h[1][col1])*sc1 + sh1, 0.0f), ah[3], al[3]);
        tf32_split(fmaxf(__ldg(&h[2][col0])*sc0 + sh0, 0.0f), ah[4], al[4]);
        tf32_split(fmaxf(__ldg(&h[3][col0])*sc0 + sh0, 0.0f), ah[5], al[5]);
        tf32_split(fmaxf(__ldg(&h[2][col1])*sc1 + sh1, 0.0f), ah[6], al[6]);
        tf32_split(fmaxf(__ldg(&h[3][col1])*sc1 + sh1, 0.0f), ah[7], al[7]);
        #pragma unroll
        for (int n8 = 0; n8 < 8; ++n8) {
            ull wv = pb[k*4*WPAD + n8*8];
            u32 b0 = (u32)wv, b1v = (u32)(wv >> 32);
            mma_tf32(acc[n8][0],acc[n8][1],acc[n8][2],acc[n8][3],  ah[0],ah[1],ah[2],ah[3], b0,b1v);
            mma_tf32(acc2[n8][0],acc2[n8][1],acc2[n8][2],acc2[n8][3], ah[4],ah[5],ah[6],ah[7], b0,b1v);
            mma_tf32(acc[n8][0],acc[n8][1],acc[n8][2],acc[n8][3],  al[0],al[1],al[2],al[3], b0,b1v);
            mma_tf32(acc2[n8][0],acc2[n8][1],acc2[n8][2],acc2[n8][3], al[4],al[5],al[6],al[7], b0,b1v);
        }
    }
    #pragma unroll
    for (int n8 = 0; n8 < 8; ++n8)
        LAYER_STATS_EPI4(acc, acc2, g_h2, n8);
    __syncthreads();
    if (tid < 64) {
        float S = 0.0f, Q = 0.0f;
        #pragma unroll
        for (int ww = 0; ww < 8; ++ww) { S += sm_s[ww*64 + tid]; Q += sm_q[ww*64 + tid]; }
        atomicAdd(&g_stats[128 + tid], S);
        atomicAdd(&g_stats[192 + tid], Q);
    }
}

// ---------------- layer3: relu(BN2(h2)) @ W3^T + b3, fused pool + stats --------------
// 32 rows/warp = exactly one centroid -> pool finishes in-warp (no smem mx/mn).
__global__ __launch_bounds__(256, 2) void k_layer3(const float* __restrict__ b3,
                                                   const float* __restrict__ g2,
                                                   const float* __restrict__ be2) {
    __shared__ ull ws64[64*WPAD];
    __shared__ float bs[128], sc[64], sh[64];
    __shared__ float sm_s[512], sm_q[512];
    int tid = threadIdx.x;
    int lane = tid & 31, w = tid >> 5;
    int g = lane >> 2, c = lane & 3;

    for (int i = tid; i < 32*128; i += 256) {
        int r = i >> 7, n = i & 127;
        ws64[(n >> 6)*32*WPAD + r*WPAD + (n & 63)] = g_w3p[i];
    }
    if (tid < 128) bs[tid] = b3[tid];
    if (tid < 64) {
        float m = g_stats[128+tid] * INV_ROWS;
        float v = g_stats[192+tid] * INV_ROWS - m*m;
        float scv = g2[tid] * rsqrtf(v + EPSV);
        sc[tid] = scv;
        sh[tid] = be2[tid] - m*scv;
    }
    __syncthreads();

    size_t base = (size_t)blockIdx.x*256 + w*32;
    size_t r0 = base + g;
    size_t cent = (size_t)blockIdx.x*8 + w;
    const float* h[4];
    #pragma unroll
    for (int j = 0; j < 4; ++j) h[j] = &g_h2[(r0 + j*8)*64];

    #pragma unroll
    for (int oh = 0; oh < 2; ++oh) {
        if (oh == 1) __syncthreads();   // sm_s/sm_q reused; prior reads done
        const ull* pb = &ws64[oh*32*WPAD + c*WPAD + g];
        float acc[8][4], acc2[8][4];
        #pragma unroll
        for (int n8 = 0; n8 < 8; ++n8) {
            float b0v = bs[oh*64 + n8*8 + 2*c], b1v = bs[oh*64 + n8*8 + 2*c + 1];
            acc[n8][0] = b0v; acc[n8][1] = b1v; acc[n8][2] = b0v; acc[n8][3] = b1v;
            acc2[n8][0] = b0v; acc2[n8][1] = b1v; acc2[n8][2] = b0v; acc2[n8][3] = b1v;
        }
        #pragma unroll
        for (int k = 0; k < 8; ++k) {
            int col0 = c + 8*k, col1 = col0 + 4;
            float sc0 = sc[col0], sh0 = sh[col0];
            float sc1 = sc[col1], sh1 = sh[col1];
            u32 ah[8], al[8];
            tf32_split(fmaxf(__ldg(&h[0][col0])*sc0 + sh0, 0.0f), ah[0], al[0]);
            tf32_split(fmaxf(__ldg(&h[1][col0])*sc0 + sh0, 0.0f), ah[1], al[1]);
            tf32_split(fmaxf(__ldg(&h[0][col1])*sc1 + sh1, 0.0f), ah[2], al[2]);
            tf32_split(fmaxf(__ldg(&h[1][col1])*sc1 + sh1, 0.0f), ah[3], al[3]);
            tf32_split(fmaxf(__ldg(&h[2][col0])*sc0 + sh0, 0.0f), ah[4], al[4]);
            tf32_split(fmaxf(__ldg(&h[3][col0])*sc0 + sh0, 0.0f), ah[5], al[5]);
            tf32_split(fmaxf(__ldg(&h[2][col1])*sc1 + sh1, 0.0f), ah[6], al[6]);
            tf32_split(fmaxf(__ldg(&h[3][col1])*sc1 + sh1, 0.0f), ah[7], al[7]);
            #pragma unroll
            for (int n8 = 0; n8 < 8; ++n8) {
                ull wv = pb[k*4*WPAD + n8*8];
                u32 b0 = (u32)wv, b1v = (u32)(wv >> 32);
                mma_tf32(acc[n8][0],acc[n8][1],acc[n8][2],acc[n8][3],  ah[0],ah[1],ah[2],ah[3], b0,b1v);
                mma_tf32(acc2[n8][0],acc2[n8][1],acc2[n8][2],acc2[n8][3], ah[4],ah[5],ah[6],ah[7], b0,b1v);
                mma_tf32(acc[n8][0],acc[n8][1],acc[n8][2],acc[n8][3],  al[0],al[1],al[2],al[3], b0,b1v);
                mma_tf32(acc2[n8][0],acc2[n8][1],acc2[n8][2],acc2[n8][3], al[4],al[5],al[6],al[7], b0,b1v);
            }
        }
        #pragma unroll
        for (int n8 = 0; n8 < 8; ++n8) {
            float mx0 = fmaxf(fmaxf(acc[n8][0], acc[n8][2]), fmaxf(acc2[n8][0], acc2[n8][2]));
            float mn0 = fminf(fminf(acc[n8][0], acc[n8][2]), fminf(acc2[n8][0], acc2[n8][2]));
            float mx1 = fmaxf(fmaxf(acc[n8][1], acc[n8][3]), fmaxf(acc2[n8][1], acc2[n8][3]));
            float mn1 = fminf(fminf(acc[n8][1], acc[n8][3]), fminf(acc2[n8][1], acc2[n8][3]));
            float s0 = (acc[n8][0] + acc[n8][2]) + (acc2[n8][0] + acc2[n8][2]);
            float s1 = (acc[n8][1] + acc[n8][3]) + (acc2[n8][1] + acc2[n8][3]);
            float q0 = (acc[n8][0]*acc[n8][0] + acc[n8][2]*acc[n8][2])
                     + (acc2[n8][0]*acc2[n8][0] + acc2[n8][2]*acc2[n8][2]);
            float q1 = (acc[n8][1]*acc[n8][1] + acc[n8][3]*acc[n8][3])
                     + (acc2[n8][1]*acc2[n8][1] + acc2[n8][3]*acc2[n8][3]);
            #pragma unroll
            for (int m = 4; m <= 16; m <<= 1) {
                mx0 = fmaxf(mx0, __shfl_xor_sync(0xffffffffu, mx0, m));
                mn0 = fminf(mn0, __shfl_xor_sync(0xffffffffu, mn0, m));
                mx1 = fmaxf(mx1, __shfl_xor_sync(0xffffffffu, mx1, m));
                mn1 = fminf(mn1, __shfl_xor_sync(0xffffffffu, mn1, m));
                s0 += __shfl_xor_sync(0xffffffffu, s0, m);
                s1 += __shfl_xor_sync(0xffffffffu, s1, m);
                q0 += __shfl_xor_sync(0xffffffffu, q0, m);
                q1 += __shfl_xor_sync(0xffffffffu, q1, m);
            }
            if (lane < 4) {
                int col0 = n8*8 + 2*c;
                *(float2*)&g_mx[cent*128 + oh*64 + col0] = make_float2(mx0, mx1);
                *(float2*)&g_mn[cent*128 + oh*64 + col0] = make_float2(mn0, mn1);
                sm_s[w*64 + col0] = s0; sm_s[w*64 + col0 + 1] = s1;
                sm_q[w*64 + col0] = q0; sm_q[w*64 + col0 + 1] = q1;
            }
        }
        __syncthreads();
        if (tid < 64) {
            float S = 0.0f, Q = 0.0f;
            #pragma unroll
            for (int ww = 0; ww < 8; ++ww) { S += sm_s[ww*64 + tid]; Q += sm_q[ww*64 + tid]; }
            atomicAdd(&g_stats[256 + oh*64 + tid], S);
            atomicAdd(&g_stats[384 + oh*64 + tid], Q);
        }
    }
}

// ---------------- apply BN3 affine to pooled max/min, transpose-store ----------------
__global__ __launch_bounds__(256) void k_apply(const float* __restrict__ g3,
                                               const float* __restrict__ be3,
                                               float* __restrict__ outp) {
    int i = blockIdx.x*256 + threadIdx.x;      // 16384*128
    int c = i & 127;
    int bp = i >> 7;
    int b = bp >> 11, p = bp & (NPT-1);
    float m = g_stats[256+c] * INV_ROWS;
    float v = g_stats[384+c] * INV_ROWS - m*m;
    float scv = g3[c] * rsqrtf(v + EPSV);
    float sh = be3[c] - m*scv;
    float pick = (scv >= 0.0f) ? g_mx[i] : g_mn[i];
    outp[((size_t)b*128 + c)*NPT + p] = pick*scv + sh;
}

// ---------------- launch ----------------
extern "C" void kernel_launch(void* const* d_in, const int* in_sizes, int n_in,
                              void* d_out, int out_size) {
    const float* xyz    = (const float*)d_in[0];
    const float* points = (const float*)d_in[1];
    const int*   sidx   = (const int*)d_in[2];
    const float* W1 = (const float*)d_in[3];
    const float* b1 = (const float*)d_in[4];
    const float* g1 = (const float*)d_in[5];
    const float* be1 = (const float*)d_in[6];
    const float* W2 = (const float*)d_in[7];
    const float* b2 = (const float*)d_in[8];
    const float* g2 = (const float*)d_in[9];
    const float* be2 = (const float*)d_in[10];
    const float* W3 = (const float*)d_in[11];
    const float* b3 = (const float*)d_in[12];
    const float* g3 = (const float*)d_in[13];
    const float* be3 = (const float*)d_in[14];

    float* outq = (float*)d_out;                 // (B,3,NPT)
    float* outp = outq + (size_t)BB*3*NPT;       // (B,128,NPT)

    const int prep_total = BB*NN + 36*64 + 32*64 + 32*128;
    k_prep<<<(prep_total + 255)/256, 256>>>(xyz, sidx, W1, W2, W3, outq);
    k_xpose<<<BB*NN/128, 256>>>(points);
    k_knn<<<dim3(NPT/16, BB), 256>>>(xyz, sidx);
    k_layer1<<<ROWS/256, 256>>>(xyz, sidx, b1);
    k_layer2<<<ROWS/256, 256>>>(b2, g1, be1);
    k_layer3<<<ROWS/256, 256>>>(b3, g2, be2);
    k_apply<<<(BB*NPT*128)/256, 256>>>(g3, be3, outp);
}

// round 17
// speedup vs baseline: 1.6456x; 1.1232x over previous
#include <cuda_runtime.h>

#define BB 8
#define NN 16384
#define NPT 2048
#define NS 32
#define ROWS (BB*NPT*NS)   /* 524288 */
#define EPSV 1e-5f
#define INV_ROWS (1.0f/524288.0f)
#define WPAD 68            /* u64 row stride: 2*68 % 32 == 8 -> conflict-free LDS.64 */
#define NBIN 2048

typedef unsigned long long ull;
typedef unsigned int u32;

// ---------------- static device scratch ----------------
__device__ float4 g_pxyz[BB*NN];                       // packed (x,y,z,0.5*|p|^2), orig order
__device__ float4 g_sx4[BB*NN];                        // x-sorted points
__device__ int    g_sorig[BB*NN];                      // sorted -> orig index
__device__ int    g_rank[BB*NN];                       // orig -> sorted rank
__device__ u32    g_xmm[BB*2];                         // per-batch mono(x) min/max
__device__ u32    g_hist[BB*NBIN], g_hoff[BB*NBIN], g_hcur[BB*NBIN];
__device__ u32    g_qhist[BB*NBIN], g_qoff[BB*NBIN], g_qcur[BB*NBIN];
__device__ int    g_qsort[BB*NPT];                     // queries sorted by x-rank
__device__ float  g_ptst[(size_t)BB*NN*64];            // points transposed [b][n][c]
__device__ int    g_idx[BB*NPT*NS];                    // knn indices
__device__ float  g_h1[(size_t)ROWS*64];
__device__ float  g_h2[(size_t)ROWS*64];
__device__ float  g_mx[BB*NPT*128];
__device__ float  g_mn[BB*NPT*128];
__device__ float  g_stats[512];
__device__ ull    g_w1p[36*64];
__device__ ull    g_w2p[32*64];
__device__ ull    g_w3p[32*128];

// ---------------- helpers ----------------
__device__ __forceinline__ unsigned mono_map(float v) {
    unsigned u = __float_as_uint(v);
    return (u & 0x80000000u) ? ~u : (u | 0x80000000u);
}
__device__ __forceinline__ float unmono(u32 m) {
    u32 bits = (m & 0x80000000u) ? (m & 0x7FFFFFFFu) : ~m;
    return __uint_as_float(bits);
}
__device__ __forceinline__ void binparams(int b, float& xmin, float& scale) {
    xmin = unmono(g_xmm[b*2+0]);
    float xmax = unmono(g_xmm[b*2+1]);
    float range = fmaxf(xmax - xmin, 1e-6f);
    scale = ((float)NBIN / range) * 0.999999f;
}
__device__ __forceinline__ u32 f2tf32(float f) {
    u32 r;
    asm("cvt.rna.tf32.f32 %0, %1;" : "=r"(r) : "f"(f));
    return r;
}
__device__ __forceinline__ void tf32_split(float f, u32& hi, u32& lo) {
    hi = f2tf32(f);
    lo = f2tf32(f - __uint_as_float(hi));
}
__device__ __forceinline__ void mma_tf32(float& d0, float& d1, float& d2, float& d3,
                                         u32 a0, u32 a1, u32 a2, u32 a3,
                                         u32 b0, u32 b1) {
    asm volatile(
        "mma.sync.aligned.m16n8k8.row.col.f32.tf32.tf32.f32 "
        "{%0,%1,%2,%3}, {%4,%5,%6,%7}, {%8,%9}, {%0,%1,%2,%3};\n"
        : "+f"(d0), "+f"(d1), "+f"(d2), "+f"(d3)
        : "r"(a0), "r"(a1), "r"(a2), "r"(a3), "r"(b0), "r"(b1));
}

// ---------------- init: reset per-batch x min/max ----------------
__global__ void k_init() {
    int t = threadIdx.x;
    if (t < BB) { g_xmm[t*2] = 0xFFFFFFFFu; g_xmm[t*2+1] = 0u; }
}

// ---------------- prep: zero + pxyz pack + x-minmax + gatherq + weight pack ---------
__global__ void k_prep(const float* __restrict__ xyz,
                       const int* __restrict__ sidx,
                       const float* __restrict__ W1, const float* __restrict__ W2,
                       const float* __restrict__ W3, float* __restrict__ outq) {
    int i = blockIdx.x*256 + threadIdx.x;
    if (i < 512) g_stats[i] = 0.0f;
    if (i < BB*NBIN) { g_hist[i] = 0u; g_qhist[i] = 0u; }
    if (i < BB*3*NPT) {
        int p = i & (NPT-1);
        int bc = i >> 11;
        outq[i] = xyz[bc*NN + sidx[p]];
    }
    float xv = 0.0f;
    if (i < BB*NN) {
        int b = i >> 14, n = i & (NN-1);
        float x = xyz[(b*3+0)*NN + n];
        float y = xyz[(b*3+1)*NN + n];
        float z = xyz[(b*3+2)*NN + n];
        g_pxyz[i] = make_float4(x, y, z, 0.5f*(x*x + y*y + z*z));
        xv = x;
    } else {
        int wi = i - BB*NN;
        if (wi < 36*64) {
            int r = wi >> 6, n = wi & 63;
            int k = r >> 2, c = r & 3;
            int kk0 = 8*k + c, kk1 = kk0 + 4;
            float w0 = 0.0f, w1 = 0.0f;
            if (kk0 < 64)      w0 = W1[n*67 + 3 + kk0];
            else if (kk0 < 67) w0 = W1[n*67 + (kk0 - 64)];
            if (kk1 < 64)      w1 = W1[n*67 + 3 + kk1];
            else if (kk1 < 67) w1 = W1[n*67 + (kk1 - 64)];
            g_w1p[wi] = ((ull)f2tf32(w1) << 32) | f2tf32(w0);
        } else if (wi < 36*64 + 32*64) {
            int j = wi - 36*64;
            int r = j >> 6, n = j & 63;
            int k = r >> 2, c = r & 3;
            g_w2p[j] = ((ull)f2tf32(W2[n*64 + 8*k + c + 4]) << 32)
                     | f2tf32(W2[n*64 + 8*k + c]);
        } else if (wi < 36*64 + 32*64 + 32*128) {
            int j = wi - 36*64 - 32*64;
            int r = j >> 7, n = j & 127;
            int k = r >> 2, c = r & 3;
            g_w3p[j] = ((ull)f2tf32(W3[n*64 + 8*k + c + 4]) << 32)
                     | f2tf32(W3[n*64 + 8*k + c]);
        }
    }
    if (blockIdx.x < (BB*NN)/256) {
        u32 umin = mono_map(xv), umax = umin;
        #pragma unroll
        for (int m = 16; m > 0; m >>= 1) {
            umin = min(umin, __shfl_xor_sync(0xffffffffu, umin, m));
            umax = max(umax, __shfl_xor_sync(0xffffffffu, umax, m));
        }
        __shared__ u32 smin[8], smax[8];
        if ((threadIdx.x & 31) == 0) { smin[threadIdx.x>>5] = umin; smax[threadIdx.x>>5] = umax; }
        __syncthreads();
        if (threadIdx.x == 0) {
            u32 mn = smin[0], mx = smax[0];
            #pragma unroll
            for (int j = 1; j < 8; ++j) { mn = min(mn, smin[j]); mx = max(mx, smax[j]); }
            int b = (blockIdx.x*256) >> 14;
            atomicMin(&g_xmm[b*2+0], mn);
            atomicMax(&g_xmm[b*2+1], mx);
        }
    }
}

// ---------------- histogram of point x bins ----------------
__global__ __launch_bounds__(256) void k_hist() {
    int i = blockIdx.x*256 + threadIdx.x;
    int b = i >> 14;
    float xmin, scale; binparams(b, xmin, scale);
    float x = g_pxyz[i].x;
    int bin = min(NBIN-1, max(0, (int)((x - xmin)*scale)));
    atomicAdd(&g_hist[b*NBIN + bin], 1u);
}

// ---------------- exclusive prefix over NBIN bins (generic) ----------------
__global__ __launch_bounds__(512) void k_scan(const u32* __restrict__ hist,
                                              u32* __restrict__ hoff,
                                              u32* __restrict__ hcur) {
    int b = blockIdx.x, tid = threadIdx.x, lane = tid & 31, wp = tid >> 5;
    int base = b*NBIN + tid*4;
    u32 v0 = hist[base], v1 = hist[base+1], v2 = hist[base+2], v3 = hist[base+3];
    u32 tot = v0 + v1 + v2 + v3;
    u32 inc = tot;
    #pragma unroll
    for (int d = 1; d < 32; d <<= 1) {
        u32 o = __shfl_up_sync(0xffffffffu, inc, d);
        if (lane >= d) inc += o;
    }
    __shared__ u32 ws[16];
    if (lane == 31) ws[wp] = inc;
    __syncthreads();
    if (tid < 16) {
        u32 x = ws[tid];
        u32 ix = x;
        #pragma unroll
        for (int d = 1; d < 16; d <<= 1) {
            u32 o = __shfl_up_sync(0xffffu, ix, d);
            if (tid >= d) ix += o;
        }
        ws[tid] = ix - x;
    }
    __syncthreads();
    u32 excl = ws[wp] + inc - tot;
    hoff[base] = excl;            hcur[base] = excl;
    hoff[base+1] = excl+v0;       hcur[base+1] = excl+v0;
    hoff[base+2] = excl+v0+v1;    hcur[base+2] = excl+v0+v1;
    hoff[base+3] = excl+v0+v1+v2; hcur[base+3] = excl+v0+v1+v2;
}

// ---------------- scatter points into x-sorted order + record ranks ----------------
__global__ __launch_bounds__(256) void k_scatter() {
    int i = blockIdx.x*256 + threadIdx.x;
    int b = i >> 14, n = i & (NN-1);
    float xmin, scale; binparams(b, xmin, scale);
    float4 P = g_pxyz[i];
    int bin = min(NBIN-1, max(0, (int)((P.x - xmin)*scale)));
    u32 pos = atomicAdd(&g_hcur[b*NBIN + bin], 1u);
    g_sx4[(size_t)b*NN + pos] = P;
    g_sorig[(size_t)b*NN + pos] = n;
    g_rank[(size_t)b*NN + n] = (int)pos;
}

// ---------------- query sort by rank: histogram then scatter ----------------
__global__ __launch_bounds__(256) void k_qhist(const int* __restrict__ sidx) {
    int i = blockIdx.x*256 + threadIdx.x;   // < BB*NPT
    int b = i >> 11, q = i & (NPT-1);
    int rank = g_rank[(size_t)b*NN + sidx[q]];
    atomicAdd(&g_qhist[b*NBIN + (rank >> 3)], 1u);
}
__global__ __launch_bounds__(256) void k_qscatter(const int* __restrict__ sidx) {
    int i = blockIdx.x*256 + threadIdx.x;   // < BB*NPT
    int b = i >> 11, q = i & (NPT-1);
    int rank = g_rank[(size_t)b*NN + sidx[q]];
    u32 pos = atomicAdd(&g_qcur[b*NBIN + (rank >> 3)], 1u);
    g_qsort[b*NPT + pos] = q;
}

// ---------------- warp 64-bit shuffles / bitonic / flush (champion) ----------------
__device__ __forceinline__ ull shfl_xor_u64(ull v, int m) {
    u32 lo = (u32)v, hi = (u32)(v >> 32);
    lo = __shfl_xor_sync(0xffffffffu, lo, m);
    hi = __shfl_xor_sync(0xffffffffu, hi, m);
    return ((ull)hi << 32) | lo;
}
__device__ __forceinline__ ull shfl_idx_u64(ull v, int src) {
    u32 lo = (u32)v, hi = (u32)(v >> 32);
    lo = __shfl_sync(0xffffffffu, lo, src);
    hi = __shfl_sync(0xffffffffu, hi, src);
    return ((ull)hi << 32) | lo;
}
__device__ __forceinline__ ull bitonic_sort32(ull v, int lane) {
    #pragma unroll
    for (int k = 2; k <= 32; k <<= 1) {
        #pragma unroll
        for (int j = k >> 1; j > 0; j >>= 1) {
            ull o = shfl_xor_u64(v, j);
            bool lower  = (lane & j) == 0;
            bool dirUp  = (lane & k) == 0;
            bool takeMin = (lower == dirUp);
            bool sw = takeMin ? (o < v) : (o > v);
            v = sw ? o : v;
        }
    }
    return v;
}
__device__ __forceinline__ void knn_flush(ull& top, int& cnt, float& thr,
                                          ull* cb, int lane) {
    for (int base = 0; base < cnt; base += 32) {
        int idx = base + lane;
        ull s = (idx < cnt) ? cb[idx] : ~0ull;
        s = bitonic_sort32(s, lane);
        ull r = shfl_idx_u64(s, 31 - lane);
        ull m = (top < r) ? top : r;
        #pragma unroll
        for (int j = 16; j > 0; j >>= 1) {
            ull o = shfl_xor_u64(m, j);
            bool lower = (lane & j) == 0;
            bool sw = lower ? (o < m) : (o > m);
            m = sw ? o : m;
        }
        top = m;
    }
    cnt = 0;
    ull k31 = shfl_idx_u64(top, 31);
    unsigned u = (unsigned)(k31 >> 32);
    float t;
    if (u == 0xFFFFFFFFu) {
        t = __int_as_float(0x7F800000);
    } else {
        unsigned bits = (u & 0x80000000u) ? (u & 0x7FFFFFFFu) : ~u;
        t = __uint_as_float(bits);
    }
    thr = t;
}

// ---------------- knn: sorted queries, tile-windowed scan, champion inner loop -------
__global__ __launch_bounds__(256) void k_knn3(const int* __restrict__ sidx) {
    __shared__ float4 sp[1024];                       // 16KB
    __shared__ int    si[1024];                       // 4KB
    __shared__ ull cbuf[16*128];                      // 16KB
    __shared__ float swlo[8], swhi[8];
    __shared__ int sq[16];
    __shared__ int st0;
    int tid = threadIdx.x, lane = tid & 31, w = tid >> 5;
    int b = blockIdx.y;
    unsigned lml = (1u << lane) - 1u;
    ull* cb0 = &cbuf[(w*2+0)*128];
    ull* cb1 = &cbuf[(w*2+1)*128];

    if (tid < 16) sq[tid] = g_qsort[b*NPT + blockIdx.x*16 + tid];
    __syncthreads();
    if (tid == 0) st0 = g_rank[(size_t)b*NN + sidx[sq[8]]] >> 10;
    int q0 = sq[w*2], q1 = sq[w*2+1];
    int s0 = sidx[q0], s1 = sidx[q1];
    float4 Q0 = g_pxyz[b*NN + s0];
    float4 Q1 = g_pxyz[b*NN + s1];
    float qx0 = Q0.x, qy0 = Q0.y, qz0 = Q0.z, c20 = Q0.w;
    float qx1 = Q1.x, qy1 = Q1.y, qz1 = Q1.z, c21 = Q1.w;
    const float INFF = __int_as_float(0x7F800000);
    ull top0 = ~0ull, top1 = ~0ull;
    float thr0 = INFF, thr1 = INFF;
    float u0 = INFF, u1 = INFF;
    int c0 = 0, c1 = 0;
    const float4* px = &g_sx4[(size_t)b*NN];
    const int*    po = &g_sorig[(size_t)b*NN];
    __syncthreads();
    int t0 = st0;

#define SCAN_TILE(TT)                                                             \
    do {                                                                          \
        int tb = (TT) << 10;                                                      \
        __syncthreads();                                                          \
        _Pragma("unroll")                                                         \
        for (int j = 0; j < 4; ++j) {                                             \
            sp[tid + j*256] = px[tb + tid + j*256];                               \
            si[tid + j*256] = po[tb + tid + j*256];                               \
        }                                                                         \
        __syncthreads();                                                          \
        for (int jj = 0; jj < 1024; jj += 64) {                                   \
            if ((c0 | c1) > 64) {                                                 \
                if (c0 > 64) { knn_flush(top0, c0, thr0, cb0, lane); u0 = __fadd_ru(thr0, -c20); } \
                if (c1 > 64) { knn_flush(top1, c1, thr1, cb1, lane); u1 = __fadd_ru(thr1, -c21); } \
            }                                                                     \
            _Pragma("unroll")                                                     \
            for (int h = 0; h < 2; ++h) {                                         \
                int j = jj + h*32 + lane;                                         \
                float4 p = sp[j];                                                 \
                float d0 = __fmaf_rn(-qx0, p.x, p.w);                             \
                d0 = __fmaf_rn(-qy0, p.y, d0);                                    \
                d0 = __fmaf_rn(-qz0, p.z, d0);                                    \
                float d1 = __fmaf_rn(-qx1, p.x, p.w);                             \
                d1 = __fmaf_rn(-qy1, p.y, d1);                                    \
                d1 = __fmaf_rn(-qz1, p.z, d1);                                    \
                bool pr0 = d0 < u0;                                               \
                bool pr1 = d1 < u1;                                               \
                if (__any_sync(0xffffffffu, pr0 || pr1)) {                        \
                    unsigned m0 = __ballot_sync(0xffffffffu, pr0);                \
                    unsigned m1 = __ballot_sync(0xffffffffu, pr1);                \
                    if (pr0) {                                                    \
                        unsigned ub = mono_map(d0 + c20);                         \
                        cb0[c0 + __popc(m0 & lml)] = ((ull)ub << 32) | (unsigned)si[j]; \
                    }                                                             \
                    if (pr1) {                                                    \
                        unsigned ub = mono_map(d1 + c21);                         \
                        cb1[c1 + __popc(m1 & lml)] = ((ull)ub << 32) | (unsigned)si[j]; \
                    }                                                             \
                    c0 += __popc(m0);                                             \
                    c1 += __popc(m1);                                             \
                }                                                                 \
            }                                                                     \
        }                                                                         \
    } while (0)

    // ---- phase A: one tile around the block's median query ----
    SCAN_TILE(t0);
    knn_flush(top0, c0, thr0, cb0, lane); u0 = __fadd_ru(thr0, -c20);
    knn_flush(top1, c1, thr1, cb1, lane); u1 = __fadd_ru(thr1, -c21);

    // ---- block window from per-query radii ----
    float r0 = sqrtf(fmaxf(2.0f*thr0, 0.0f))*1.0001f + 1e-6f;
    float r1 = sqrtf(fmaxf(2.0f*thr1, 0.0f))*1.0001f + 1e-6f;
    if (lane == 0) {
        swlo[w] = fminf(qx0 - r0, qx1 - r1);
        swhi[w] = fmaxf(qx0 + r0, qx1 + r1);
    }
    __syncthreads();
    float bxlo = swlo[0], bxhi = swhi[0];
    #pragma unroll
    for (int j = 1; j < 8; ++j) { bxlo = fminf(bxlo, swlo[j]); bxhi = fmaxf(bxhi, swhi[j]); }
    float xmin, scale; binparams(b, xmin, scale);
    int blo = min(NBIN-1, max(0, (int)((bxlo - xmin)*scale) - 1));
    int bhi = min(NBIN-1, max(0, (int)((bxhi - xmin)*scale) + 1));
    int lo = (int)g_hoff[b*NBIN + blo];
    int hi = (bhi >= NBIN-1) ? NN : (int)g_hoff[b*NBIN + bhi + 1];
    int tfirst = lo >> 10, tlast = (hi - 1) >> 10;

    // ---- phase B: remaining tiles in window ----
    for (int tt = tfirst; tt <= tlast; ++tt) {
        if (tt == t0) continue;
        SCAN_TILE(tt);
    }
    knn_flush(top0, c0, thr0, cb0, lane);
    knn_flush(top1, c1, thr1, cb1, lane);
    g_idx[(b*NPT + q0)*NS + lane] = (int)(top0 & 0xffffffffu);
    g_idx[(b*NPT + q1)*NS + lane] = (int)(top1 & 0xffffffffu);
#undef SCAN_TILE
}

// ---------------- tiled transpose points (B,C,N) -> (B,N,C) ----------------
__global__ __launch_bounds__(256) void k_xpose(const float* __restrict__ pts) {
    __shared__ float tile[64*129];
    int blk = blockIdx.x;
    int b = blk >> 7;
    int nbase = (blk & 127) * 128;
    int tid = threadIdx.x;
    int nl = tid & 127, rh = tid >> 7;
    #pragma unroll
    for (int pass = 0; pass < 32; ++pass) {
        int row = rh + pass*2;
        tile[row*129 + nl] = pts[((size_t)(b*64 + row))*NN + nbase + nl];
    }
    __syncthreads();
    int cg = (tid & 15) * 4, nh = tid >> 4;
    #pragma unroll
    for (int pass = 0; pass < 8; ++pass) {
        int n = nh + pass*16;
        float4 v = make_float4(tile[cg*129 + n], tile[(cg+1)*129 + n],
                               tile[(cg+2)*129 + n], tile[(cg+3)*129 + n]);
        *(float4*)&g_ptst[((size_t)(b*NN + nbase + n))*64 + cg] = v;
    }
}

// ============================================================================
// Layer kernels: k-OUTER, M=32 rows/warp (R16 champion, unchanged).
// ============================================================================

#define LAYER_STATS_EPI4(A, A2, hout, nn8)                                        \
    do {                                                                          \
        *(float2*)&hout[(r0     )*64 + (nn8)*8 + 2*c] = make_float2(A[nn8][0], A[nn8][1]); \
        *(float2*)&hout[(r0 +  8)*64 + (nn8)*8 + 2*c] = make_float2(A[nn8][2], A[nn8][3]); \
        *(float2*)&hout[(r0 + 16)*64 + (nn8)*8 + 2*c] = make_float2(A2[nn8][0], A2[nn8][1]); \
        *(float2*)&hout[(r0 + 24)*64 + (nn8)*8 + 2*c] = make_float2(A2[nn8][2], A2[nn8][3]); \
        float s0 = (A[nn8][0] + A[nn8][2]) + (A2[nn8][0] + A2[nn8][2]);           \
        float s1 = (A[nn8][1] + A[nn8][3]) + (A2[nn8][1] + A2[nn8][3]);           \
        float q0 = (A[nn8][0]*A[nn8][0] + A[nn8][2]*A[nn8][2])                    \
                 + (A2[nn8][0]*A2[nn8][0] + A2[nn8][2]*A2[nn8][2]);               \
        float q1 = (A[nn8][1]*A[nn8][1] + A[nn8][3]*A[nn8][3])                    \
                 + (A2[nn8][1]*A2[nn8][1] + A2[nn8][3]*A2[nn8][3]);               \
        _Pragma("unroll")                                                         \
        for (int m = 4; m <= 16; m <<= 1) {                                       \
            s0 += __shfl_xor_sync(0xffffffffu, s0, m);                            \
            s1 += __shfl_xor_sync(0xffffffffu, s1, m);                            \
            q0 += __shfl_xor_sync(0xffffffffu, q0, m);                            \
            q1 += __shfl_xor_sync(0xffffffffu, q1, m);                            \
        }                                                                         \
        if (lane < 4) {                                                           \
            int col0 = (nn8)*8 + 2*c;                                             \
            sm_s[w*64 + col0] = s0; sm_s[w*64 + col0 + 1] = s1;                   \
            sm_q[w*64 + col0] = q0; sm_q[w*64 + col0 + 1] = q1;                   \
        }                                                                         \
    } while (0)

__global__ __launch_bounds__(256, 2) void k_layer1(const float* __restrict__ xyz,
                                                   const int* __restrict__ sidx,
                                                   const float* __restrict__ b1) {
    __shared__ ull ws64[36*WPAD];
    __shared__ float bs[64];
    __shared__ float sm_s[512], sm_q[512];
    int tid = threadIdx.x;
    for (int i = tid; i < 36*64; i += 256)
        ws64[(i >> 6)*WPAD + (i & 63)] = g_w1p[i];
    if (tid < 64) bs[tid] = b1[tid];
    __syncthreads();

    int lane = tid & 31, w = tid >> 5;
    int g = lane >> 2, c = lane & 3;
    size_t base = (size_t)blockIdx.x*256 + w*32;
    size_t r0 = base + g;
    int b = (int)(base >> 16);
    int p0 = ((int)base >> 5) & (NPT-1);
    int s = sidx[p0];
    float qx = xyz[(b*3+0)*NN + s], qy = xyz[(b*3+1)*NN + s], qz = xyz[(b*3+2)*NN + s];
    int nn[4];
    const float* f[4];
    float ex[4], ey[4], ez[4];
    #pragma unroll
    for (int j = 0; j < 4; ++j) {
        nn[j] = g_idx[r0 + j*8];
        float4 P = g_pxyz[b*NN + nn[j]];
        ex[j] = P.x - qx; ey[j] = P.y - qy; ez[j] = P.z - qz;
        f[j] = &g_ptst[(size_t)(b*NN + nn[j])*64];
    }

    float acc[8][4], acc2[8][4];
    #pragma unroll
    for (int n8 = 0; n8 < 8; ++n8) {
        float b0v = bs[n8*8 + 2*c], b1v = bs[n8*8 + 2*c + 1];
        acc[n8][0] = b0v; acc[n8][1] = b1v; acc[n8][2] = b0v; acc[n8][3] = b1v;
        acc2[n8][0] = b0v; acc2[n8][1] = b1v; acc2[n8][2] = b0v; acc2[n8][3] = b1v;
    }

    const ull* pb = &ws64[c*WPAD + g];
    #pragma unroll
    for (int k = 0; k < 9; ++k) {
        u32 ah[8], al[8];
        if (k < 8) {
            int col0 = c + 8*k, col1 = col0 + 4;
            tf32_split(__ldg(&f[0][col0]), ah[0], al[0]);
            tf32_split(__ldg(&f[1][col0]), ah[1], al[1]);
            tf32_split(__ldg(&f[0][col1]), ah[2], al[2]);
            tf32_split(__ldg(&f[1][col1]), ah[3], al[3]);
            tf32_split(__ldg(&f[2][col0]), ah[4], al[4]);
            tf32_split(__ldg(&f[3][col0]), ah[5], al[5]);
            tf32_split(__ldg(&f[2][col1]), ah[6], al[6]);
            tf32_split(__ldg(&f[3][col1]), ah[7], al[7]);
        } else {
            #pragma unroll
            for (int j = 0; j < 4; ++j) {
                float e = (c == 0) ? ex[j] : (c == 1) ? ey[j] : (c == 2) ? ez[j] : 0.0f;
                int slot = (j < 2) ? j : (2 + j);
                tf32_split(e, ah[slot], al[slot]);
            }
            ah[2] = 0; al[2] = 0; ah[3] = 0; al[3] = 0;
            ah[6] = 0; al[6] = 0; ah[7] = 0; al[7] = 0;
        }
        #pragma unroll
        for (int n8 = 0; n8 < 8; ++n8) {
            ull wv = pb[k*4*WPAD + n8*8];
            u32 b0 = (u32)wv, b1v = (u32)(wv >> 32);
            mma_tf32(acc[n8][0],acc[n8][1],acc[n8][2],acc[n8][3],  ah[0],ah[1],ah[2],ah[3], b0,b1v);
            mma_tf32(acc2[n8][0],acc2[n8][1],acc2[n8][2],acc2[n8][3], ah[4],ah[5],ah[6],ah[7], b0,b1v);
            mma_tf32(acc[n8][0],acc[n8][1],acc[n8][2],acc[n8][3],  al[0],al[1],al[2],al[3], b0,b1v);
            mma_tf32(acc2[n8][0],acc2[n8][1],acc2[n8][2],acc2[n8][3], al[4],al[5],al[6],al[7], b0,b1v);
        }
    }
    #pragma unroll
    for (int n8 = 0; n8 < 8; ++n8)
        LAYER_STATS_EPI4(acc, acc2, g_h1, n8);
    __syncthreads();
    if (tid < 64) {
        float S = 0.0f, Q = 0.0f;
        #pragma unroll
        for (int ww = 0; ww < 8; ++ww) { S += sm_s[ww*64 + tid]; Q += sm_q[ww*64 + tid]; }
        atomicAdd(&g_stats[tid], S);
        atomicAdd(&g_stats[64 + tid], Q);
    }
}

__global__ __launch_bounds__(256, 2) void k_layer2(const float* __restrict__ b2,
                                                   const float* __restrict__ g1,
                                                   const float* __restrict__ be1) {
    __shared__ ull ws64[32*WPAD];
    __shared__ float bs[64], sc[64], sh[64];
    __shared__ float sm_s[512], sm_q[512];
    int tid = threadIdx.x;
    for (int i = tid; i < 32*64; i += 256)
        ws64[(i >> 6)*WPAD + (i & 63)] = g_w2p[i];
    if (tid < 64) {
        bs[tid] = b2[tid];
        float m = g_stats[tid] * INV_ROWS;
        float v = g_stats[64+tid] * INV_ROWS - m*m;
        float scv = g1[tid] * rsqrtf(v + EPSV);
        sc[tid] = scv;
        sh[tid] = be1[tid] - m*scv;
    }
    __syncthreads();

    int lane = tid & 31, w = tid >> 5;
    int g = lane >> 2, c = lane & 3;
    size_t base = (size_t)blockIdx.x*256 + w*32;
    size_t r0 = base + g;
    const float* h[4];
    #pragma unroll
    for (int j = 0; j < 4; ++j) h[j] = &g_h1[(r0 + j*8)*64];

    float acc[8][4], acc2[8][4];
    #pragma unroll
    for (int n8 = 0; n8 < 8; ++n8) {
        float b0v = bs[n8*8 + 2*c], b1v = bs[n8*8 + 2*c + 1];
        acc[n8][0] = b0v; acc[n8][1] = b1v; acc[n8][2] = b0v; acc[n8][3] = b1v;
        acc2[n8][0] = b0v; acc2[n8][1] = b1v; acc2[n8][2] = b0v; acc2[n8][3] = b1v;
    }

    const ull* pb = &ws64[c*WPAD + g];
    #pragma unroll
    for (int k = 0; k < 8; ++k) {
        int col0 = c + 8*k, col1 = col0 + 4;
        float sc0 = sc[col0], sh0 = sh[col0];
        float sc1 = sc[col1], sh1 = sh[col1];
        u32 ah[8], al[8];
        tf32_split(fmaxf(__ldg(&h[0][col0])*sc0 + sh0, 0.0f), ah[0], al[0]);
        tf32_split(fmaxf(__ldg(&h[1][col0])*sc0 + sh0, 0.0f), ah[1], al[1]);
        tf32_split(fmaxf(__ldg(&h[0][col1])*sc1 + sh1, 0.0f), ah[2], al[2]);
        tf32_split(fmaxf(__ldg(&h[1][col1])*sc1 + sh1, 0.0f), ah[3], al[3]);
        tf32_split(fmaxf(__ldg(&h[2][col0])*sc0 + sh0, 0.0f), ah[4], al[4]);
        tf32_split(fmaxf(__ldg(&h[3][col0])*sc0 + sh0, 0.0f), ah[5], al[5]);
        tf32_split(fmaxf(__ldg(&h[2][col1])*sc1 + sh1, 0.0f), ah[6], al[6]);
        tf32_split(fmaxf(__ldg(&h[3][col1])*sc1 + sh1, 0.0f), ah[7], al[7]);
        #pragma unroll
        for (int n8 = 0; n8 < 8; ++n8) {
            ull wv = pb[k*4*WPAD + n8*8];
            u32 b0 = (u32)wv, b1v = (u32)(wv >> 32);
            mma_tf32(acc[n8][0],acc[n8][1],acc[n8][2],acc[n8][3],  ah[0],ah[1],ah[2],ah[3], b0,b1v);
            mma_tf32(acc2[n8][0],acc2[n8][1],acc2[n8][2],acc2[n8][3], ah[4],ah[5],ah[6],ah[7], b0,b1v);
            mma_tf32(acc[n8][0],acc[n8][1],acc[n8][2],acc[n8][3],  al[0],al[1],al[2],al[3], b0,b1v);
            mma_tf32(acc2[n8][0],acc2[n8][1],acc2[n8][2],acc2[n8][3], al[4],al[5],al[6],al[7], b0,b1v);
        }
    }
    #pragma unroll
    for (int n8 = 0; n8 < 8; ++n8)
        LAYER_STATS_EPI4(acc, acc2, g_h2, n8);
    __syncthreads();
    if (tid < 64) {
        float S = 0.0f, Q = 0.0f;
        #pragma unroll
        for (int ww = 0; ww < 8; ++ww) { S += sm_s[ww*64 + tid]; Q += sm_q[ww*64 + tid]; }
        atomicAdd(&g_stats[128 + tid], S);
        atomicAdd(&g_stats[192 + tid], Q);
    }
}

__global__ __launch_bounds__(256, 2) void k_layer3(const float* __restrict__ b3,
                                                   const float* __restrict__ g2,
                                                   const float* __restrict__ be2) {
    __shared__ ull ws64[64*WPAD];
    __shared__ float bs[128], sc[64], sh[64];
    __shared__ float sm_s[512], sm_q[512];
    int tid = threadIdx.x;
    int lane = tid & 31, w = tid >> 5;
    int g = lane >> 2, c = lane & 3;

    for (int i = tid; i < 32*128; i += 256) {
        int r = i >> 7, n = i & 127;
        ws64[(n >> 6)*32*WPAD + r*WPAD + (n & 63)] = g_w3p[i];
    }
    if (tid < 128) bs[tid] = b3[tid];
    if (tid < 64) {
        float m = g_stats[128+tid] * INV_ROWS;
        float v = g_stats[192+tid] * INV_ROWS - m*m;
        float scv = g2[tid] * rsqrtf(v + EPSV);
        sc[tid] = scv;
        sh[tid] = be2[tid] - m*scv;
    }
    __syncthreads();

    size_t base = (size_t)blockIdx.x*256 + w*32;
    size_t r0 = base + g;
    size_t cent = (size_t)blockIdx.x*8 + w;
    const float* h[4];
    #pragma unroll
    for (int j = 0; j < 4; ++j) h[j] = &g_h2[(r0 + j*8)*64];

    #pragma unroll
    for (int oh = 0; oh < 2; ++oh) {
        if (oh == 1) __syncthreads();
        const ull* pb = &ws64[oh*32*WPAD + c*WPAD + g];
        float acc[8][4], acc2[8][4];
        #pragma unroll
        for (int n8 = 0; n8 < 8; ++n8) {
            float b0v = bs[oh*64 + n8*8 + 2*c], b1v = bs[oh*64 + n8*8 + 2*c + 1];
            acc[n8][0] = b0v; acc[n8][1] = b1v; acc[n8][2] = b0v; acc[n8][3] = b1v;
            acc2[n8][0] = b0v; acc2[n8][1] = b1v; acc2[n8][2] = b0v; acc2[n8][3] = b1v;
        }
        #pragma unroll
        for (int k = 0; k < 8; ++k) {
            int col0 = c + 8*k, col1 = col0 + 4;
            float sc0 = sc[col0], sh0 = sh[col0];
            float sc1 = sc[col1], sh1 = sh[col1];
            u32 ah[8], al[8];
            tf32_split(fmaxf(__ldg(&h[0][col0])*sc0 + sh0, 0.0f), ah[0], al[0]);
            tf32_split(fmaxf(__ldg(&h[1][col0])*sc0 + sh0, 0.0f), ah[1], al[1]);
            tf32_split(fmaxf(__ldg(&h[0][col1])*sc1 + sh1, 0.0f), ah[2], al[2]);
            tf32_split(fmaxf(__ldg(&h[1][col1])*sc1 + sh1, 0.0f), ah[3], al[3]);
            tf32_split(fmaxf(__ldg(&h[2][col0])*sc0 + sh0, 0.0f), ah[4], al[4]);
            tf32_split(fmaxf(__ldg(&h[3][col0])*sc0 + sh0, 0.0f), ah[5], al[5]);
            tf32_split(fmaxf(__ldg(&h[2][col1])*sc1 + sh1, 0.0f), ah[6], al[6]);
            tf32_split(fmaxf(__ldg(&h[3][col1])*sc1 + sh1, 0.0f), ah[7], al[7]);
            #pragma unroll
            for (int n8 = 0; n8 < 8; ++n8) {
                ull wv = pb[k*4*WPAD + n8*8];
                u32 b0 = (u32)wv, b1v = (u32)(wv >> 32);
                mma_tf32(acc[n8][0],acc[n8][1],acc[n8][2],acc[n8][3],  ah[0],ah[1],ah[2],ah[3], b0,b1v);
                mma_tf32(acc2[n8][0],acc2[n8][1],acc2[n8][2],acc2[n8][3], ah[4],ah[5],ah[6],ah[7], b0,b1v);
                mma_tf32(acc[n8][0],acc[n8][1],acc[n8][2],acc[n8][3],  al[0],al[1],al[2],al[3], b0,b1v);
                mma_tf32(acc2[n8][0],acc2[n8][1],acc2[n8][2],acc2[n8][3], al[4],al[5],al[6],al[7], b0,b1v);
            }
        }
        #pragma unroll
        for (int n8 = 0; n8 < 8; ++n8) {
            float mx0 = fmaxf(fmaxf(acc[n8][0], acc[n8][2]), fmaxf(acc2[n8][0], acc2[n8][2]));
            float mn0 = fminf(fminf(acc[n8][0], acc[n8][2]), fminf(acc2[n8][0], acc2[n8][2]));
            float mx1 = fmaxf(fmaxf(acc[n8][1], acc[n8][3]), fmaxf(acc2[n8][1], acc2[n8][3]));
            float mn1 = fminf(fminf(acc[n8][1], acc[n8][3]), fminf(acc2[n8][1], acc2[n8][3]));
            float s0 = (acc[n8][0] + acc[n8][2]) + (acc2[n8][0] + acc2[n8][2]);
            float s1 = (acc[n8][1] + acc[n8][3]) + (acc2[n8][1] + acc2[n8][3]);
            float q0 = (acc[n8][0]*acc[n8][0] + acc[n8][2]*acc[n8][2])
                     + (acc2[n8][0]*acc2[n8][0] + acc2[n8][2]*acc2[n8][2]);
            float q1 = (acc[n8][1]*acc[n8][1] + acc[n8][3]*acc[n8][3])
                     + (acc2[n8][1]*acc2[n8][1] + acc2[n8][3]*acc2[n8][3]);
            #pragma unroll
            for (int m = 4; m <= 16; m <<= 1) {
                mx0 = fmaxf(mx0, __shfl_xor_sync(0xffffffffu, mx0, m));
                mn0 = fminf(mn0, __shfl_xor_sync(0xffffffffu, mn0, m));
                mx1 = fmaxf(mx1, __shfl_xor_sync(0xffffffffu, mx1, m));
                mn1 = fminf(mn1, __shfl_xor_sync(0xffffffffu, mn1, m));
                s0 += __shfl_xor_sync(0xffffffffu, s0, m);
                s1 += __shfl_xor_sync(0xffffffffu, s1, m);
                q0 += __shfl_xor_sync(0xffffffffu, q0, m);
                q1 += __shfl_xor_sync(0xffffffffu, q1, m);
            }
            if (lane < 4) {
                int col0 = n8*8 + 2*c;
                *(float2*)&g_mx[cent*128 + oh*64 + col0] = make_float2(mx0, mx1);
                *(float2*)&g_mn[cent*128 + oh*64 + col0] = make_float2(mn0, mn1);
                sm_s[w*64 + col0] = s0; sm_s[w*64 + col0 + 1] = s1;
                sm_q[w*64 + col0] = q0; sm_q[w*64 + col0 + 1] = q1;
            }
        }
        __syncthreads();
        if (tid < 64) {
            float S = 0.0f, Q = 0.0f;
            #pragma unroll
            for (int ww = 0; ww < 8; ++ww) { S += sm_s[ww*64 + tid]; Q += sm_q[ww*64 + tid]; }
            atomicAdd(&g_stats[256 + oh*64 + tid], S);
            atomicAdd(&g_stats[384 + oh*64 + tid], Q);
        }
    }
}

// ---------------- apply BN3 affine to pooled max/min, transpose-store ----------------
__global__ __launch_bounds__(256) void k_apply(const float* __restrict__ g3,
                                               const float* __restrict__ be3,
                                               float* __restrict__ outp) {
    int i = blockIdx.x*256 + threadIdx.x;
    int c = i & 127;
    int bp = i >> 7;
    int b = bp >> 11, p = bp & (NPT-1);
    float m = g_stats[256+c] * INV_ROWS;
    float v = g_stats[384+c] * INV_ROWS - m*m;
    float scv = g3[c] * rsqrtf(v + EPSV);
    float sh = be3[c] - m*scv;
    float pick = (scv >= 0.0f) ? g_mx[i] : g_mn[i];
    outp[((size_t)b*128 + c)*NPT + p] = pick*scv + sh;
}

// ---------------- launch ----------------
extern "C" void kernel_launch(void* const* d_in, const int* in_sizes, int n_in,
                              void* d_out, int out_size) {
    const float* xyz    = (const float*)d_in[0];
    const float* points = (const float*)d_in[1];
    const int*   sidx   = (const int*)d_in[2];
    const float* W1 = (const float*)d_in[3];
    const float* b1 = (const float*)d_in[4];
    const float* g1 = (const float*)d_in[5];
    const float* be1 = (const float*)d_in[6];
    const float* W2 = (const float*)d_in[7];
    const float* b2 = (const float*)d_in[8];
    const float* g2 = (const float*)d_in[9];
    const float* be2 = (const float*)d_in[10];
    const float* W3 = (const float*)d_in[11];
    const float* b3 = (const float*)d_in[12];
    const float* g3 = (const float*)d_in[13];
    const float* be3 = (const float*)d_in[14];

    float* outq = (float*)d_out;                 // (B,3,NPT)
    float* outp = outq + (size_t)BB*3*NPT;       // (B,128,NPT)

    u32 *hist, *hoff, *hcur, *qhist, *qoff, *qcur;
    cudaGetSymbolAddress((void**)&hist,  g_hist);
    cudaGetSymbolAddress((void**)&hoff,  g_hoff);
    cudaGetSymbolAddress((void**)&hcur,  g_hcur);
    cudaGetSymbolAddress((void**)&qhist, g_qhist);
    cudaGetSymbolAddress((void**)&qoff,  g_qoff);
    cudaGetSymbolAddress((void**)&qcur,  g_qcur);

    const int prep_total = BB*NN + 36*64 + 32*64 + 32*128;
    k_init<<<1, 32>>>();
    k_prep<<<(prep_total + 255)/256, 256>>>(xyz, sidx, W1, W2, W3, outq);
    k_xpose<<<BB*NN/128, 256>>>(points);
    k_hist<<<BB*NN/256, 256>>>();
    k_scan<<<BB, 512>>>(hist, hoff, hcur);
    k_scatter<<<BB*NN/256, 256>>>();
    k_qhist<<<BB*NPT/256, 256>>>(sidx);
    k_scan<<<BB, 512>>>(qhist, qoff, qcur);
    k_qscatter<<<BB*NPT/256, 256>>>(sidx);
    k_knn3<<<dim3(NPT/16, BB), 256>>>(sidx);
    k_layer1<<<ROWS/256, 256>>>(xyz, sidx, b1);
    k_layer2<<<ROWS/256, 256>>>(b2, g1, be1);
    k_layer3<<<ROWS/256, 256>>>(b3, g2, be2);
    k_apply<<<(BB*NPT*128)/256, 256>>>(g3, be3, outp);
}